// round 4
// baseline (speedup 1.0000x reference)
#include <cuda_runtime.h>
#include <math.h>

// Problem constants
#define NN  32
#define PPd 6
#define Cd  128
#define Td  64
#define Vd  25
#define Sd  3
#define CId 32
#define NPd   (NN*PPd)        // 192
#define NPVd  (NPd*Vd)        // 4800
#define SLAB  (Cd*Td)         // 8192 floats per (n,p,v)
#define QKOd  (2*Sd*CId)      // 192
#define TOTd  (NPVd*SLAB)     // 39321600
#define CNTf  307200.0f       // N*P*T*V
#define EPSf  1e-5f
#define NEGf  0.1f

// Scratch
__device__ float g_x0[TOTd];
__device__ float g_x1[TOTd];
__device__ float g_y1[TOTd];
__device__ float g_z [TOTd];
__device__ float g_qk [NPVd*QKOd*Td];
__device__ float g_att[NN*Sd*PPd*Td*Td];
__device__ float g_sum[Cd];
__device__ float g_sq [Cd];

__device__ __forceinline__ float lrelu(float x){ return x >= 0.f ? x : NEGf*x; }

__device__ __forceinline__ float to_tf32(float x){
  unsigned u; asm("cvt.rna.tf32.f32 %0, %1;" : "=r"(u) : "f"(x));
  return __uint_as_float(u);
}
__device__ __forceinline__ void st_tf32_f4(float* dst, float4 v){
  dst[0]=to_tf32(v.x); dst[1]=to_tf32(v.y); dst[2]=to_tf32(v.z); dst[3]=to_tf32(v.w);
}
__device__ __forceinline__ void mma8(float c[4], const float a[4], const float b[2]){
  asm volatile(
    "mma.sync.aligned.m16n8k8.row.col.f32.tf32.tf32.f32 "
    "{%0,%1,%2,%3},{%4,%5,%6,%7},{%8,%9},{%0,%1,%2,%3};\n"
    : "+f"(c[0]),"+f"(c[1]),"+f"(c[2]),"+f"(c[3])
    : "r"(__float_as_uint(a[0])),"r"(__float_as_uint(a[1])),
      "r"(__float_as_uint(a[2])),"r"(__float_as_uint(a[3])),
      "r"(__float_as_uint(b[0])),"r"(__float_as_uint(b[1])));
}

// ---------------------------------------------------------------------------
// Input transpose: x[(n,p)][c][t][v]  ->  g_x0[(n,p)][v][c][t]
__global__ void k_tin(const float* __restrict__ x){
  __shared__ float tile[32][33];
  int np = blockIdx.y, m0 = blockIdx.x*32;
  const float* src = x + (size_t)np*(Cd*Td*Vd);
  float* dst = g_x0 + (size_t)np*(Vd*SLAB);
  int tx = threadIdx.x, ty = threadIdx.y;
  #pragma unroll
  for (int k=0;k<4;k++){
    int m = m0 + ty + k*8;
    if (tx < Vd) tile[ty+k*8][tx] = src[(size_t)m*Vd + tx];
  }
  __syncthreads();
  #pragma unroll
  for (int k=0;k<4;k++){
    int v = ty + k*8;
    if (v < Vd) dst[(size_t)v*SLAB + m0 + tx] = tile[tx][v];
  }
}

// Output transpose: src[(n,p)][v][c][t] -> dst[(n,p)][c][t][v]
__global__ void k_tout(const float* __restrict__ srcb, float* __restrict__ dst){
  __shared__ float tile[32][33];
  int np = blockIdx.y, m0 = blockIdx.x*32;
  const float* src = srcb + (size_t)np*(Vd*SLAB);
  float* d = dst + (size_t)np*(Cd*Td*Vd);
  int tx = threadIdx.x, ty = threadIdx.y;
  #pragma unroll
  for (int k=0;k<4;k++){
    int v = ty + k*8;
    if (v < Vd) tile[v][tx] = src[(size_t)v*SLAB + m0 + tx];
  }
  __syncthreads();
  #pragma unroll
  for (int k=0;k<4;k++){
    int m = m0 + ty + k*8;
    if (tx < Vd) d[(size_t)m*Vd + tx] = tile[tx][ty + k*8];
  }
}

// ---------------------------------------------------------------------------
// QK conv (tensor): per npv  Out[192x64] = W_in[192x128] * X[128x64] + b
// warps: 4 in M (48 rows) x 2 in N (32 cols). K chunked by 32.
__global__ void __launch_bounds__(256,2) k_qk(const float* __restrict__ in,
                                              const float* __restrict__ w_in,
                                              const float* __restrict__ b_in){
  extern __shared__ float sm[];
  float* Xs = sm;              // 128*68
  float* Wc = sm + 128*68;     // 192*36
  int npv = blockIdx.x;
  int tid = threadIdx.x, lane = tid&31, w = tid>>5;
  int m0 = (w&3)*48, n0 = (w>>2)*32;
  int gid = lane>>2, tig = lane&3;

  const float4* xin4 = (const float4*)(in + (size_t)npv*SLAB);
  for (int i=tid;i<2048;i+=256){
    int r = i>>4, c4 = (i&15)<<2;
    st_tf32_f4(&Xs[r*68 + c4], xin4[i]);
  }
  float acc[3][4][4];
  #pragma unroll
  for (int mf=0;mf<3;mf++)
    #pragma unroll
    for (int nf=0;nf<4;nf++){ acc[mf][nf][0]=acc[mf][nf][1]=acc[mf][nf][2]=acc[mf][nf][3]=0.f; }

  for (int c0=0;c0<128;c0+=32){
    __syncthreads();
    for (int i=tid;i<1536;i+=256){
      int o = i>>3, c4 = (i&7)<<2;
      st_tf32_f4(&Wc[o*36 + c4], *(const float4*)&w_in[(size_t)o*128 + c0 + c4]);
    }
    __syncthreads();
    #pragma unroll
    for (int kt=0;kt<4;kt++){
      int kk = kt*8;
      float a[3][4], b[4][2];
      #pragma unroll
      for (int mf=0;mf<3;mf++){
        int r = m0 + mf*16 + gid;
        a[mf][0] = Wc[r*36 + kk + tig];
        a[mf][1] = Wc[(r+8)*36 + kk + tig];
        a[mf][2] = Wc[r*36 + kk + 4 + tig];
        a[mf][3] = Wc[(r+8)*36 + kk + 4 + tig];
      }
      #pragma unroll
      for (int nf=0;nf<4;nf++){
        int col = n0 + nf*8 + gid;
        b[nf][0] = Xs[(c0+kk+tig)*68 + col];
        b[nf][1] = Xs[(c0+kk+4+tig)*68 + col];
      }
      #pragma unroll
      for (int mf=0;mf<3;mf++)
        #pragma unroll
        for (int nf=0;nf<4;nf++) mma8(acc[mf][nf], a[mf], b[nf]);
    }
  }
  float* outp = g_qk + (size_t)npv*QKOd*Td;
  #pragma unroll
  for (int mf=0;mf<3;mf++){
    int r = m0 + mf*16 + gid;
    float b0 = b_in[r], b1 = b_in[r+8];
    #pragma unroll
    for (int nf=0;nf<4;nf++){
      int col = n0 + nf*8 + 2*tig;
      *(float2*)&outp[r*64 + col]     = make_float2(acc[mf][nf][0]+b0, acc[mf][nf][1]+b0);
      *(float2*)&outp[(r+8)*64 + col] = make_float2(acc[mf][nf][2]+b1, acc[mf][nf][3]+b1);
    }
  }
}

// ---------------------------------------------------------------------------
// Attention: per (n,s,p): att[t,q] = bias + tanh( sum_{c,v} q[c,t,v]k[c,q,v] / 800 )*alpha
__global__ void __launch_bounds__(256) k_att(const float* __restrict__ attb,
                                             const float* __restrict__ alphat){
  __shared__ float qv[CId*Td];
  __shared__ float kv[CId*Td];
  int b = blockIdx.x;               // ((n*S+s)*P+p)
  int p = b % PPd; int s = (b/PPd) % Sd; int n = b/(PPd*Sd);
  int np = n*PPd + p;
  int tid = threadIdx.x, tx = tid & 15, ty = tid >> 4;
  float acc[4][4];
  #pragma unroll
  for (int i=0;i<4;i++){ acc[i][0]=acc[i][1]=acc[i][2]=acc[i][3]=0.f; }
  for (int v=0; v<Vd; v++){
    size_t base = ((size_t)(np*Vd + v))*QKOd*Td;
    const float4* q4 = (const float4*)(g_qk + base + (size_t)(s*CId)*Td);
    const float4* k4 = (const float4*)(g_qk + base + (size_t)(Sd*CId + s*CId)*Td);
    __syncthreads();
    for (int i=tid; i<CId*Td/4; i+=256){ ((float4*)qv)[i]=q4[i]; ((float4*)kv)[i]=k4[i]; }
    __syncthreads();
    #pragma unroll 4
    for (int c=0;c<CId;c++){
      float qr[4], kr[4];
      #pragma unroll
      for (int i=0;i<4;i++) qr[i]=qv[c*Td + ty*4 + i];
      #pragma unroll
      for (int j=0;j<4;j++) kr[j]=kv[c*Td + tx*4 + j];
      #pragma unroll
      for (int i=0;i<4;i++)
        #pragma unroll
        for (int j=0;j<4;j++) acc[i][j] += qr[i]*kr[j];
    }
  }
  float al = alphat[s];
  float* attp = g_att + (size_t)b*Td*Td;
  const float* bp = attb + (size_t)s*Td*Td;
  #pragma unroll
  for (int i=0;i<4;i++){
    int t = ty*4 + i;
    #pragma unroll
    for (int j=0;j<4;j++){
      int q = tx*4 + j;
      attp[t*Td+q] = bp[t*Td+q] + tanhf(acc[i][j]*(1.f/800.f))*al;
    }
  }
}

// ---------------------------------------------------------------------------
// Fused attention-apply + S*C->C conv + BN stats (tensor).
// per npv: for s: Ys[128x64] = X*A_s (K=64);  Z += W_s[128x128]*Ys (K=128)
__global__ void __launch_bounds__(256,2) k_av(const float* __restrict__ in,
                                              const float* __restrict__ w_out,
                                              const float* __restrict__ b_out){
  extern __shared__ float sm[];
  float* Xs = sm;              // 128*68 = 8704
  float* Ys = sm + 8704;       // 128*68 = 8704
  float* As = sm + 17408;      // 64*68  = 4352
  float* Wc = sm + 21760;      // 128*36 = 4608
  int npv = blockIdx.x;
  int np = npv / Vd;
  int p = np % PPd, n = np / PPd;
  int tid = threadIdx.x, lane = tid&31, w = tid>>5;
  int m0 = (w&3)*32, n0 = (w>>2)*32;
  int gid = lane>>2, tig = lane&3;

  const float4* xin4 = (const float4*)(in + (size_t)npv*SLAB);
  for (int i=tid;i<2048;i+=256){
    int r = i>>4, c4 = (i&15)<<2;
    st_tf32_f4(&Xs[r*68 + c4], xin4[i]);
  }
  float zacc[2][4][4];
  #pragma unroll
  for (int mf=0;mf<2;mf++)
    #pragma unroll
    for (int nf=0;nf<4;nf++){ zacc[mf][nf][0]=zacc[mf][nf][1]=zacc[mf][nf][2]=zacc[mf][nf][3]=0.f; }

  for (int s=0;s<Sd;s++){
    __syncthreads();
    const float4* a4 = (const float4*)(g_att + ((size_t)((n*Sd+s)*PPd+p))*Td*Td);
    for (int i=tid;i<1024;i+=256){
      int r = i>>4, c4 = (i&15)<<2;
      st_tf32_f4(&As[r*68 + c4], a4[i]);
    }
    __syncthreads();

    // Stage 1: Ys = X * A_s   (m=c rows of X, n=q, k=t)
    float yacc[2][4][4];
    #pragma unroll
    for (int mf=0;mf<2;mf++)
      #pragma unroll
      for (int nf=0;nf<4;nf++){ yacc[mf][nf][0]=yacc[mf][nf][1]=yacc[mf][nf][2]=yacc[mf][nf][3]=0.f; }
    #pragma unroll
    for (int kt=0;kt<8;kt++){
      int kk = kt*8;
      float a[2][4], b[4][2];
      #pragma unroll
      for (int mf=0;mf<2;mf++){
        int r = m0 + mf*16 + gid;
        a[mf][0] = Xs[r*68 + kk + tig];
        a[mf][1] = Xs[(r+8)*68 + kk + tig];
        a[mf][2] = Xs[r*68 + kk + 4 + tig];
        a[mf][3] = Xs[(r+8)*68 + kk + 4 + tig];
      }
      #pragma unroll
      for (int nf=0;nf<4;nf++){
        int col = n0 + nf*8 + gid;
        b[nf][0] = As[(kk+tig)*68 + col];
        b[nf][1] = As[(kk+4+tig)*68 + col];
      }
      #pragma unroll
      for (int mf=0;mf<2;mf++)
        #pragma unroll
        for (int nf=0;nf<4;nf++) mma8(yacc[mf][nf], a[mf], b[nf]);
    }
    // write Ys (tf32-rounded)
    #pragma unroll
    for (int mf=0;mf<2;mf++){
      int r = m0 + mf*16 + gid;
      #pragma unroll
      for (int nf=0;nf<4;nf++){
        int col = n0 + nf*8 + 2*tig;
        Ys[r*68 + col]       = to_tf32(yacc[mf][nf][0]);
        Ys[r*68 + col + 1]   = to_tf32(yacc[mf][nf][1]);
        Ys[(r+8)*68 + col]   = to_tf32(yacc[mf][nf][2]);
        Ys[(r+8)*68 + col+1] = to_tf32(yacc[mf][nf][3]);
      }
    }

    // Stage 2: Z += W_s * Ys   (m=o, k=c chunked by 32, n=q)
    for (int c0=0;c0<128;c0+=32){
      __syncthreads();
      for (int i=tid;i<1024;i+=256){
        int o = i>>3, c4 = (i&7)<<2;
        st_tf32_f4(&Wc[o*36 + c4],
                   *(const float4*)&w_out[(size_t)o*(Sd*Cd) + s*Cd + c0 + c4]);
      }
      __syncthreads();
      #pragma unroll
      for (int kt=0;kt<4;kt++){
        int kk = kt*8;
        float a[2][4], b[4][2];
        #pragma unroll
        for (int mf=0;mf<2;mf++){
          int r = m0 + mf*16 + gid;
          a[mf][0] = Wc[r*36 + kk + tig];
          a[mf][1] = Wc[(r+8)*36 + kk + tig];
          a[mf][2] = Wc[r*36 + kk + 4 + tig];
          a[mf][3] = Wc[(r+8)*36 + kk + 4 + tig];
        }
        #pragma unroll
        for (int nf=0;nf<4;nf++){
          int col = n0 + nf*8 + gid;
          b[nf][0] = Ys[(c0+kk+tig)*68 + col];
          b[nf][1] = Ys[(c0+kk+4+tig)*68 + col];
        }
        #pragma unroll
        for (int mf=0;mf<2;mf++)
          #pragma unroll
          for (int nf=0;nf<4;nf++) mma8(zacc[mf][nf], a[mf], b[nf]);
      }
    }
  }

  // epilogue: bias, store g_z, BN stats
  float* zp = g_z + (size_t)npv*SLAB;
  #pragma unroll
  for (int mf=0;mf<2;mf++){
    int r = m0 + mf*16 + gid;
    float bo0 = b_out[r], bo1 = b_out[r+8];
    float s0a=0.f, s0b=0.f, s1a=0.f, s1b=0.f;
    #pragma unroll
    for (int nf=0;nf<4;nf++){
      int col = n0 + nf*8 + 2*tig;
      float z00 = zacc[mf][nf][0]+bo0, z01 = zacc[mf][nf][1]+bo0;
      float z10 = zacc[mf][nf][2]+bo1, z11 = zacc[mf][nf][3]+bo1;
      *(float2*)&zp[r*64 + col]     = make_float2(z00, z01);
      *(float2*)&zp[(r+8)*64 + col] = make_float2(z10, z11);
      s0a += z00+z01; s0b += z00*z00+z01*z01;
      s1a += z10+z11; s1b += z10*z10+z11*z11;
    }
    #pragma unroll
    for (int off=1; off<4; off<<=1){
      s0a += __shfl_xor_sync(0xffffffffu, s0a, off);
      s0b += __shfl_xor_sync(0xffffffffu, s0b, off);
      s1a += __shfl_xor_sync(0xffffffffu, s1a, off);
      s1b += __shfl_xor_sync(0xffffffffu, s1b, off);
    }
    if (tig==0){
      atomicAdd(&g_sum[r], s0a);   atomicAdd(&g_sq[r], s0b);
      atomicAdd(&g_sum[r+8], s1a); atomicAdd(&g_sq[r+8], s1b);
    }
  }
}

// ---------------------------------------------------------------------------
// FF conv (tensor): Out[128x64] = W_ff[128x128] * X[128x64] + b, with BN stats
__global__ void __launch_bounds__(256,2) k_ff(const float* __restrict__ in,
                                              const float* __restrict__ w_ff,
                                              const float* __restrict__ b_ff){
  extern __shared__ float sm[];
  float* Xs = sm;              // 128*68
  float* Wc = sm + 8704;       // 128*36
  int npv = blockIdx.x;
  int tid = threadIdx.x, lane = tid&31, w = tid>>5;
  int m0 = (w&3)*32, n0 = (w>>2)*32;
  int gid = lane>>2, tig = lane&3;

  const float4* xin4 = (const float4*)(in + (size_t)npv*SLAB);
  for (int i=tid;i<2048;i+=256){
    int r = i>>4, c4 = (i&15)<<2;
    st_tf32_f4(&Xs[r*68 + c4], xin4[i]);
  }
  float acc[2][4][4];
  #pragma unroll
  for (int mf=0;mf<2;mf++)
    #pragma unroll
    for (int nf=0;nf<4;nf++){ acc[mf][nf][0]=acc[mf][nf][1]=acc[mf][nf][2]=acc[mf][nf][3]=0.f; }

  for (int c0=0;c0<128;c0+=32){
    __syncthreads();
    for (int i=tid;i<1024;i+=256){
      int o = i>>3, c4 = (i&7)<<2;
      st_tf32_f4(&Wc[o*36 + c4], *(const float4*)&w_ff[(size_t)o*128 + c0 + c4]);
    }
    __syncthreads();
    #pragma unroll
    for (int kt=0;kt<4;kt++){
      int kk = kt*8;
      float a[2][4], b[4][2];
      #pragma unroll
      for (int mf=0;mf<2;mf++){
        int r = m0 + mf*16 + gid;
        a[mf][0] = Wc[r*36 + kk + tig];
        a[mf][1] = Wc[(r+8)*36 + kk + tig];
        a[mf][2] = Wc[r*36 + kk + 4 + tig];
        a[mf][3] = Wc[(r+8)*36 + kk + 4 + tig];
      }
      #pragma unroll
      for (int nf=0;nf<4;nf++){
        int col = n0 + nf*8 + gid;
        b[nf][0] = Xs[(c0+kk+tig)*68 + col];
        b[nf][1] = Xs[(c0+kk+4+tig)*68 + col];
      }
      #pragma unroll
      for (int mf=0;mf<2;mf++)
        #pragma unroll
        for (int nf=0;nf<4;nf++) mma8(acc[mf][nf], a[mf], b[nf]);
    }
  }
  float* zp = g_z + (size_t)npv*SLAB;
  #pragma unroll
  for (int mf=0;mf<2;mf++){
    int r = m0 + mf*16 + gid;
    float bo0 = b_ff[r], bo1 = b_ff[r+8];
    float s0a=0.f, s0b=0.f, s1a=0.f, s1b=0.f;
    #pragma unroll
    for (int nf=0;nf<4;nf++){
      int col = n0 + nf*8 + 2*tig;
      float z00 = acc[mf][nf][0]+bo0, z01 = acc[mf][nf][1]+bo0;
      float z10 = acc[mf][nf][2]+bo1, z11 = acc[mf][nf][3]+bo1;
      *(float2*)&zp[r*64 + col]     = make_float2(z00, z01);
      *(float2*)&zp[(r+8)*64 + col] = make_float2(z10, z11);
      s0a += z00+z01; s0b += z00*z00+z01*z01;
      s1a += z10+z11; s1b += z10*z10+z11*z11;
    }
    #pragma unroll
    for (int off=1; off<4; off<<=1){
      s0a += __shfl_xor_sync(0xffffffffu, s0a, off);
      s0b += __shfl_xor_sync(0xffffffffu, s0b, off);
      s1a += __shfl_xor_sync(0xffffffffu, s1a, off);
      s1b += __shfl_xor_sync(0xffffffffu, s1b, off);
    }
    if (tig==0){
      atomicAdd(&g_sum[r], s0a);   atomicAdd(&g_sq[r], s0b);
      atomicAdd(&g_sum[r+8], s1a); atomicAdd(&g_sq[r+8], s1b);
    }
  }
}

// ---------------------------------------------------------------------------
// BN apply + residual + leaky
__global__ void k_bnres(const float* __restrict__ res, const float* __restrict__ z,
                        float* __restrict__ out,
                        const float* __restrict__ gamma, const float* __restrict__ beta){
  size_t i4 = (size_t)blockIdx.x*256 + threadIdx.x;
  int c = (int)((i4 >> 4) & 127);
  float mu  = g_sum[c] * (1.0f/CNTf);
  float var = g_sq[c]  * (1.0f/CNTf) - mu*mu;
  float sc  = gamma[c] * rsqrtf(var + EPSf);
  float sh  = beta[c] - mu*sc;
  float4 zr = ((const float4*)z)[i4];
  float4 rr = ((const float4*)res)[i4];
  float4 o;
  o.x = lrelu(rr.x + zr.x*sc + sh);
  o.y = lrelu(rr.y + zr.y*sc + sh);
  o.z = lrelu(rr.z + zr.z*sc + sh);
  o.w = lrelu(rr.w + zr.w*sc + sh);
  ((float4*)out)[i4] = o;
}

__global__ void k_zero(){
  int i = threadIdx.x;
  if (i < Cd){ g_sum[i] = 0.f; g_sq[i] = 0.f; }
}

// ---------------------------------------------------------------------------
extern "C" void kernel_launch(void* const* d_in, const int* in_sizes, int n_in,
                              void* d_out, int out_size){
  const float* x     = (const float*)d_in[0];
  const float* att1  = (const float*)d_in[1];
  const float* att2  = (const float*)d_in[2];
  const float* alpt  = (const float*)d_in[3];
  const float* w_in  = (const float*)d_in[4];
  const float* b_in  = (const float*)d_in[5];
  const float* w_out = (const float*)d_in[6];
  const float* b_out = (const float*)d_in[7];
  const float* g_o   = (const float*)d_in[8];
  const float* be_o  = (const float*)d_in[9];
  const float* w_ff  = (const float*)d_in[10];
  const float* b_ff  = (const float*)d_in[11];
  const float* g_f   = (const float*)d_in[12];
  const float* be_f  = (const float*)d_in[13];

  float *px0, *px1, *py1, *pz;
  cudaGetSymbolAddress((void**)&px0, g_x0);
  cudaGetSymbolAddress((void**)&px1, g_x1);
  cudaGetSymbolAddress((void**)&py1, g_y1);
  cudaGetSymbolAddress((void**)&pz,  g_z);

  const int SM_QK = (128*68 + 192*36)*4;                     // 62464
  const int SM_AV = (128*68 + 128*68 + 64*68 + 128*36)*4;    // 105472
  const int SM_FF = (128*68 + 128*36)*4;                     // 53248
  cudaFuncSetAttribute(k_qk, cudaFuncAttributeMaxDynamicSharedMemorySize, SM_QK);
  cudaFuncSetAttribute(k_av, cudaFuncAttributeMaxDynamicSharedMemorySize, SM_AV);
  cudaFuncSetAttribute(k_ff, cudaFuncAttributeMaxDynamicSharedMemorySize, SM_FF);

  k_tin<<<dim3(256,192), dim3(32,8)>>>(x);

  auto run_block = [&](const float* attb, const float* inb, float* outb){
    k_qk <<<NPVd,256,SM_QK>>>(inb, w_in, b_in);
    k_att<<<NN*Sd*PPd,256>>>(attb, alpt);
    k_zero<<<1,128>>>();
    k_av <<<NPVd,256,SM_AV>>>(inb, w_out, b_out);
    k_bnres<<<TOTd/4/256,256>>>(inb, pz, py1, g_o, be_o);
    k_zero<<<1,128>>>();
    k_ff <<<NPVd,256,SM_FF>>>(py1, w_ff, b_ff);
    k_bnres<<<TOTd/4/256,256>>>(py1, pz, outb, g_f, be_f);
  };

  run_block(att1, px0, px1);   // block 1: x0 -> x1
  run_block(att2, px1, px0);   // block 2: x1 -> x0

  k_tout<<<dim3(256,192), dim3(32,8)>>>(px0, (float*)d_out);
}

// round 10
// speedup vs baseline: 1.4157x; 1.4157x over previous
#include <cuda_runtime.h>
#include <cuda_fp16.h>
#include <math.h>
#include <stdint.h>

#define NN  32
#define PPd 6
#define Cd  128
#define Td  64
#define Vd  25
#define Sd  3
#define CId 32
#define NPd   (NN*PPd)
#define NPVd  (NPd*Vd)        // 4800
#define SLAB  (Cd*Td)         // 8192
#define QKOd  (2*Sd*CId)      // 192
#define TOTd  (NPVd*SLAB)
#define CNTf  307200.0f
#define EPSf  1e-5f
#define NEGf  0.1f

__device__ float g_x0[TOTd];
__device__ float g_x1[TOTd];
__device__ float g_y1[TOTd];
__device__ float g_z [TOTd];
__device__ float g_qk [NPVd*QKOd*Td];
__device__ float g_att[NN*Sd*PPd*Td*Td];
__device__ float g_sum[Cd];
__device__ float g_sq [Cd];

__device__ __forceinline__ float lrelu(float x){ return x >= 0.f ? x : NEGf*x; }

__device__ __forceinline__ uint2 pack4(float4 v){
  __half2 h0 = __floats2half2_rn(v.x, v.y);
  __half2 h1 = __floats2half2_rn(v.z, v.w);
  uint2 u; u.x = *(uint32_t*)&h0; u.y = *(uint32_t*)&h1; return u;
}
// m16n8k16 fp16 MMA, fp32 accumulate
__device__ __forceinline__ void mmah(float c[4], const uint32_t a[4], const uint32_t b[2]){
  asm volatile(
    "mma.sync.aligned.m16n8k16.row.col.f32.f16.f16.f32 "
    "{%0,%1,%2,%3},{%4,%5,%6,%7},{%8,%9},{%0,%1,%2,%3};\n"
    : "+f"(c[0]),"+f"(c[1]),"+f"(c[2]),"+f"(c[3])
    : "r"(a[0]),"r"(a[1]),"r"(a[2]),"r"(a[3]),"r"(b[0]),"r"(b[1]));
}
#define LDU32(p) (*(const uint32_t*)(p))

// ---------------------------------------------------------------------------
// Input transpose: x[(n,p)][c][t][v] -> g_x0[(n,p)][v][c][t]
__global__ void k_tin(const float* __restrict__ x){
  __shared__ float tile[32][33];
  int np = blockIdx.y, m0 = blockIdx.x*32;
  const float* src = x + (size_t)np*(Cd*Td*Vd);
  float* dst = g_x0 + (size_t)np*(Vd*SLAB);
  int tx = threadIdx.x, ty = threadIdx.y;
  #pragma unroll
  for (int k=0;k<4;k++){ int m = m0 + ty + k*8; if (tx < Vd) tile[ty+k*8][tx] = src[(size_t)m*Vd + tx]; }
  __syncthreads();
  #pragma unroll
  for (int k=0;k<4;k++){ int v = ty + k*8; if (v < Vd) dst[(size_t)v*SLAB + m0 + tx] = tile[tx][v]; }
}
__global__ void k_tout(const float* __restrict__ srcb, float* __restrict__ dst){
  __shared__ float tile[32][33];
  int np = blockIdx.y, m0 = blockIdx.x*32;
  const float* src = srcb + (size_t)np*(Vd*SLAB);
  float* d = dst + (size_t)np*(Cd*Td*Vd);
  int tx = threadIdx.x, ty = threadIdx.y;
  #pragma unroll
  for (int k=0;k<4;k++){ int v = ty + k*8; if (v < Vd) tile[v][tx] = src[(size_t)v*SLAB + m0 + tx]; }
  __syncthreads();
  #pragma unroll
  for (int k=0;k<4;k++){ int m = m0 + ty + k*8; if (tx < Vd) d[(size_t)m*Vd + tx] = tile[tx][ty + k*8]; }
}

// ---------------------------------------------------------------------------
// QK conv (fp16 mma): per npv  Out[192x64] = W_in[192x128] * X[128x64] + b
// warps: 4 in M (48 rows, 3 frags) x 2 in N (32 cols, 4 frags). K=128 -> 8 k16 steps.
__global__ void __launch_bounds__(256,2) k_qk(const float* __restrict__ in,
                                              const float* __restrict__ w_in,
                                              const float* __restrict__ b_in){
  extern __shared__ __half smh[];
  __half* Xt = smh;           // [t=64][c=128] stride 136
  __half* Wc = smh + 8704;    // [o=192][c=128] stride 136
  int npv = blockIdx.x;
  int tid = threadIdx.x, lane = tid&31, w = tid>>5;
  int m0 = (w&3)*48, n0 = (w>>2)*32;
  int gid = lane>>2, tig = lane&3;

  const float4* xin4 = (const float4*)(in + (size_t)npv*SLAB);
  for (int i=tid;i<2048;i+=256){
    int c = i>>4, t0 = (i&15)<<2; float4 v = xin4[i];
    Xt[(t0  )*136+c] = __float2half_rn(v.x);
    Xt[(t0+1)*136+c] = __float2half_rn(v.y);
    Xt[(t0+2)*136+c] = __float2half_rn(v.z);
    Xt[(t0+3)*136+c] = __float2half_rn(v.w);
  }
  for (int i=tid;i<192*32;i+=256){
    int o = i>>5, c0 = (i&31)<<2;
    *(uint2*)&Wc[o*136 + c0] = pack4(*(const float4*)&w_in[o*128 + c0]);
  }
  __syncthreads();

  float acc[3][4][4];
  #pragma unroll
  for (int mf=0;mf<3;mf++)
    #pragma unroll
    for (int nf=0;nf<4;nf++){ acc[mf][nf][0]=acc[mf][nf][1]=acc[mf][nf][2]=acc[mf][nf][3]=0.f; }

  #pragma unroll
  for (int ks=0;ks<8;ks++){
    int kk = ks*16 + 2*tig;
    uint32_t a[3][4], b[4][2];
    #pragma unroll
    for (int mf=0;mf<3;mf++){
      int r = m0 + mf*16 + gid;
      a[mf][0] = LDU32(&Wc[r*136 + kk]);
      a[mf][1] = LDU32(&Wc[(r+8)*136 + kk]);
      a[mf][2] = LDU32(&Wc[r*136 + kk + 8]);
      a[mf][3] = LDU32(&Wc[(r+8)*136 + kk + 8]);
    }
    #pragma unroll
    for (int nf=0;nf<4;nf++){
      int col = n0 + nf*8 + gid;
      b[nf][0] = LDU32(&Xt[col*136 + kk]);
      b[nf][1] = LDU32(&Xt[col*136 + kk + 8]);
    }
    #pragma unroll
    for (int mf=0;mf<3;mf++)
      #pragma unroll
      for (int nf=0;nf<4;nf++) mmah(acc[mf][nf], a[mf], b[nf]);
  }
  float* outp = g_qk + (size_t)npv*QKOd*Td;
  #pragma unroll
  for (int mf=0;mf<3;mf++){
    int r = m0 + mf*16 + gid;
    float b0 = b_in[r], b1 = b_in[r+8];
    #pragma unroll
    for (int nf=0;nf<4;nf++){
      int col = n0 + nf*8 + 2*tig;
      *(float2*)&outp[r*64 + col]     = make_float2(acc[mf][nf][0]+b0, acc[mf][nf][1]+b0);
      *(float2*)&outp[(r+8)*64 + col] = make_float2(acc[mf][nf][2]+b1, acc[mf][nf][3]+b1);
    }
  }
}

// ---------------------------------------------------------------------------
// Attention scores (scalar)
__global__ void __launch_bounds__(256) k_att(const float* __restrict__ attb,
                                             const float* __restrict__ alphat){
  __shared__ float qv[CId*Td];
  __shared__ float kv[CId*Td];
  int b = blockIdx.x;
  int p = b % PPd; int s = (b/PPd) % Sd; int n = b/(PPd*Sd);
  int np = n*PPd + p;
  int tid = threadIdx.x, tx = tid & 15, ty = tid >> 4;
  float acc[4][4];
  #pragma unroll
  for (int i=0;i<4;i++){ acc[i][0]=acc[i][1]=acc[i][2]=acc[i][3]=0.f; }
  for (int v=0; v<Vd; v++){
    size_t base = ((size_t)(np*Vd + v))*QKOd*Td;
    const float4* q4 = (const float4*)(g_qk + base + (size_t)(s*CId)*Td);
    const float4* k4 = (const float4*)(g_qk + base + (size_t)(Sd*CId + s*CId)*Td);
    __syncthreads();
    for (int i=tid; i<CId*Td/4; i+=256){ ((float4*)qv)[i]=q4[i]; ((float4*)kv)[i]=k4[i]; }
    __syncthreads();
    #pragma unroll 4
    for (int c=0;c<CId;c++){
      float qr[4], kr[4];
      #pragma unroll
      for (int i=0;i<4;i++) qr[i]=qv[c*Td + ty*4 + i];
      #pragma unroll
      for (int j=0;j<4;j++) kr[j]=kv[c*Td + tx*4 + j];
      #pragma unroll
      for (int i=0;i<4;i++)
        #pragma unroll
        for (int j=0;j<4;j++) acc[i][j] += qr[i]*kr[j];
    }
  }
  float al = alphat[s];
  float* attp = g_att + (size_t)b*Td*Td;
  const float* bp = attb + (size_t)s*Td*Td;
  #pragma unroll
  for (int i=0;i<4;i++){
    int t = ty*4 + i;
    #pragma unroll
    for (int j=0;j<4;j++){
      int q = tx*4 + j;
      attp[t*Td+q] = bp[t*Td+q] + tanhf(acc[i][j]*(1.f/800.f))*al;
    }
  }
}

// ---------------------------------------------------------------------------
// Fused att-apply + S*C->C conv + BN stats (fp16 mma).
// per npv: for s: Y[c][q] = X[c][t] * A_s[t][q]; Z += W_s[o][c] * Y
__global__ void __launch_bounds__(256,2) k_av(const float* __restrict__ in,
                                              const float* __restrict__ w_out,
                                              const float* __restrict__ b_out){
  extern __shared__ __half smh[];
  __half* Xa   = smh;           // [c=128][t=64]  stride 72 (A operand stage 1)
  __half* attT = smh + 9216;    // [q=64][t=64]   stride 72 (B operand stage 1)
  __half* Yt   = smh + 13824;   // [q=64][c=128]  stride 136 (B operand stage 2)
  __half* Wc   = smh + 22528;   // [o=128][c=128] stride 136 (A operand stage 2)
  int npv = blockIdx.x;
  int np = npv / Vd;
  int p = np % PPd, n = np / PPd;
  int tid = threadIdx.x, lane = tid&31, w = tid>>5;
  int m0 = (w&3)*32, n0 = (w>>2)*32;
  int gid = lane>>2, tig = lane&3;

  const float4* xin4 = (const float4*)(in + (size_t)npv*SLAB);
  for (int i=tid;i<2048;i+=256){
    int c = i>>4, t0 = (i&15)<<2;
    *(uint2*)&Xa[c*72 + t0] = pack4(xin4[i]);
  }
  float zacc[2][4][4];
  #pragma unroll
  for (int mf=0;mf<2;mf++)
    #pragma unroll
    for (int nf=0;nf<4;nf++){ zacc[mf][nf][0]=zacc[mf][nf][1]=zacc[mf][nf][2]=zacc[mf][nf][3]=0.f; }

  for (int s=0;s<Sd;s++){
    __syncthreads();   // prev iter reads of attT/Wc/Yt done
    const float4* a4 = (const float4*)(g_att + ((size_t)((n*Sd+s)*PPd+p))*Td*Td);
    for (int i=tid;i<1024;i+=256){
      int t = i>>4, q0 = (i&15)<<2; float4 v = a4[i];
      attT[(q0  )*72+t] = __float2half_rn(v.x);
      attT[(q0+1)*72+t] = __float2half_rn(v.y);
      attT[(q0+2)*72+t] = __float2half_rn(v.z);
      attT[(q0+3)*72+t] = __float2half_rn(v.w);
    }
    for (int i=tid;i<128*32;i+=256){
      int o = i>>5, c0 = (i&31)<<2;
      *(uint2*)&Wc[o*136 + c0] = pack4(*(const float4*)&w_out[(size_t)o*(Sd*Cd) + s*Cd + c0]);
    }
    __syncthreads();

    // Stage 1: Y = Xa * attT  (m=c, n=q, k=t, 4 k16 steps)
    float yacc[2][4][4];
    #pragma unroll
    for (int mf=0;mf<2;mf++)
      #pragma unroll
      for (int nf=0;nf<4;nf++){ yacc[mf][nf][0]=yacc[mf][nf][1]=yacc[mf][nf][2]=yacc[mf][nf][3]=0.f; }
    #pragma unroll
    for (int ks=0;ks<4;ks++){
      int kk = ks*16 + 2*tig;
      uint32_t a[2][4], b[4][2];
      #pragma unroll
      for (int mf=0;mf<2;mf++){
        int r = m0 + mf*16 + gid;
        a[mf][0] = LDU32(&Xa[r*72 + kk]);
        a[mf][1] = LDU32(&Xa[(r+8)*72 + kk]);
        a[mf][2] = LDU32(&Xa[r*72 + kk + 8]);
        a[mf][3] = LDU32(&Xa[(r+8)*72 + kk + 8]);
      }
      #pragma unroll
      for (int nf=0;nf<4;nf++){
        int col = n0 + nf*8 + gid;
        b[nf][0] = LDU32(&attT[col*72 + kk]);
        b[nf][1] = LDU32(&attT[col*72 + kk + 8]);
      }
      #pragma unroll
      for (int mf=0;mf<2;mf++)
        #pragma unroll
        for (int nf=0;nf<4;nf++) mmah(yacc[mf][nf], a[mf], b[nf]);
    }
    // write Y -> Yt[q][c] fp16
    #pragma unroll
    for (int mf=0;mf<2;mf++){
      int c = m0 + mf*16 + gid;
      #pragma unroll
      for (int nf=0;nf<4;nf++){
        int q = n0 + nf*8 + 2*tig;
        Yt[q*136 + c]       = __float2half_rn(yacc[mf][nf][0]);
        Yt[(q+1)*136 + c]   = __float2half_rn(yacc[mf][nf][1]);
        Yt[q*136 + c + 8]   = __float2half_rn(yacc[mf][nf][2]);
        Yt[(q+1)*136 + c+8] = __float2half_rn(yacc[mf][nf][3]);
      }
    }
    __syncthreads();

    // Stage 2: Z += Wc * Yt  (m=o, n=q, k=c, 8 k16 steps)
    #pragma unroll
    for (int ks=0;ks<8;ks++){
      int kk = ks*16 + 2*tig;
      uint32_t a[2][4], b[4][2];
      #pragma unroll
      for (int mf=0;mf<2;mf++){
        int r = m0 + mf*16 + gid;
        a[mf][0] = LDU32(&Wc[r*136 + kk]);
        a[mf][1] = LDU32(&Wc[(r+8)*136 + kk]);
        a[mf][2] = LDU32(&Wc[r*136 + kk + 8]);
        a[mf][3] = LDU32(&Wc[(r+8)*136 + kk + 8]);
      }
      #pragma unroll
      for (int nf=0;nf<4;nf++){
        int col = n0 + nf*8 + gid;
        b[nf][0] = LDU32(&Yt[col*136 + kk]);
        b[nf][1] = LDU32(&Yt[col*136 + kk + 8]);
      }
      #pragma unroll
      for (int mf=0;mf<2;mf++)
        #pragma unroll
        for (int nf=0;nf<4;nf++) mmah(zacc[mf][nf], a[mf], b[nf]);
    }
  }

  // epilogue: bias, store g_z, BN stats
  float* zp = g_z + (size_t)npv*SLAB;
  #pragma unroll
  for (int mf=0;mf<2;mf++){
    int r = m0 + mf*16 + gid;
    float bo0 = b_out[r], bo1 = b_out[r+8];
    float s0a=0.f, s0b=0.f, s1a=0.f, s1b=0.f;
    #pragma unroll
    for (int nf=0;nf<4;nf++){
      int col = n0 + nf*8 + 2*tig;
      float z00 = zacc[mf][nf][0]+bo0, z01 = zacc[mf][nf][1]+bo0;
      float z10 = zacc[mf][nf][2]+bo1, z11 = zacc[mf][nf][3]+bo1;
      *(float2*)&zp[r*64 + col]     = make_float2(z00, z01);
      *(float2*)&zp[(r+8)*64 + col] = make_float2(z10, z11);
      s0a += z00+z01; s0b += z00*z00+z01*z01;
      s1a += z10+z11; s1b += z10*z10+z11*z11;
    }
    #pragma unroll
    for (int off=1; off<4; off<<=1){
      s0a += __shfl_xor_sync(0xffffffffu, s0a, off);
      s0b += __shfl_xor_sync(0xffffffffu, s0b, off);
      s1a += __shfl_xor_sync(0xffffffffu, s1a, off);
      s1b += __shfl_xor_sync(0xffffffffu, s1b, off);
    }
    if (tig==0){
      atomicAdd(&g_sum[r], s0a);   atomicAdd(&g_sq[r], s0b);
      atomicAdd(&g_sum[r+8], s1a); atomicAdd(&g_sq[r+8], s1b);
    }
  }
}

// ---------------------------------------------------------------------------
// FF conv (fp16 mma): Out[128x64] = W_ff[128x128] * X[128x64] + b, BN stats
__global__ void __launch_bounds__(256,2) k_ff(const float* __restrict__ in,
                                              const float* __restrict__ w_ff,
                                              const float* __restrict__ b_ff){
  extern __shared__ __half smh[];
  __half* Xt = smh;           // [t=64][c=128] stride 136
  __half* Wc = smh + 8704;    // [o=128][c=128] stride 136
  int npv = blockIdx.x;
  int tid = threadIdx.x, lane = tid&31, w = tid>>5;
  int m0 = (w&3)*32, n0 = (w>>2)*32;
  int gid = lane>>2, tig = lane&3;

  const float4* xin4 = (const float4*)(in + (size_t)npv*SLAB);
  for (int i=tid;i<2048;i+=256){
    int c = i>>4, t0 = (i&15)<<2; float4 v = xin4[i];
    Xt[(t0  )*136+c] = __float2half_rn(v.x);
    Xt[(t0+1)*136+c] = __float2half_rn(v.y);
    Xt[(t0+2)*136+c] = __float2half_rn(v.z);
    Xt[(t0+3)*136+c] = __float2half_rn(v.w);
  }
  for (int i=tid;i<128*32;i+=256){
    int o = i>>5, c0 = (i&31)<<2;
    *(uint2*)&Wc[o*136 + c0] = pack4(*(const float4*)&w_ff[o*128 + c0]);
  }
  __syncthreads();

  float acc[2][4][4];
  #pragma unroll
  for (int mf=0;mf<2;mf++)
    #pragma unroll
    for (int nf=0;nf<4;nf++){ acc[mf][nf][0]=acc[mf][nf][1]=acc[mf][nf][2]=acc[mf][nf][3]=0.f; }

  #pragma unroll
  for (int ks=0;ks<8;ks++){
    int kk = ks*16 + 2*tig;
    uint32_t a[2][4], b[4][2];
    #pragma unroll
    for (int mf=0;mf<2;mf++){
      int r = m0 + mf*16 + gid;
      a[mf][0] = LDU32(&Wc[r*136 + kk]);
      a[mf][1] = LDU32(&Wc[(r+8)*136 + kk]);
      a[mf][2] = LDU32(&Wc[r*136 + kk + 8]);
      a[mf][3] = LDU32(&Wc[(r+8)*136 + kk + 8]);
    }
    #pragma unroll
    for (int nf=0;nf<4;nf++){
      int col = n0 + nf*8 + gid;
      b[nf][0] = LDU32(&Xt[col*136 + kk]);
      b[nf][1] = LDU32(&Xt[col*136 + kk + 8]);
    }
    #pragma unroll
    for (int mf=0;mf<2;mf++)
      #pragma unroll
      for (int nf=0;nf<4;nf++) mmah(acc[mf][nf], a[mf], b[nf]);
  }
  float* zp = g_z + (size_t)npv*SLAB;
  #pragma unroll
  for (int mf=0;mf<2;mf++){
    int r = m0 + mf*16 + gid;
    float bo0 = b_ff[r], bo1 = b_ff[r+8];
    float s0a=0.f, s0b=0.f, s1a=0.f, s1b=0.f;
    #pragma unroll
    for (int nf=0;nf<4;nf++){
      int col = n0 + nf*8 + 2*tig;
      float z00 = acc[mf][nf][0]+bo0, z01 = acc[mf][nf][1]+bo0;
      float z10 = acc[mf][nf][2]+bo1, z11 = acc[mf][nf][3]+bo1;
      *(float2*)&zp[r*64 + col]     = make_float2(z00, z01);
      *(float2*)&zp[(r+8)*64 + col] = make_float2(z10, z11);
      s0a += z00+z01; s0b += z00*z00+z01*z01;
      s1a += z10+z11; s1b += z10*z10+z11*z11;
    }
    #pragma unroll
    for (int off=1; off<4; off<<=1){
      s0a += __shfl_xor_sync(0xffffffffu, s0a, off);
      s0b += __shfl_xor_sync(0xffffffffu, s0b, off);
      s1a += __shfl_xor_sync(0xffffffffu, s1a, off);
      s1b += __shfl_xor_sync(0xffffffffu, s1b, off);
    }
    if (tig==0){
      atomicAdd(&g_sum[r], s0a);   atomicAdd(&g_sq[r], s0b);
      atomicAdd(&g_sum[r+8], s1a); atomicAdd(&g_sq[r+8], s1b);
    }
  }
}

// ---------------------------------------------------------------------------
__global__ void k_bnres(const float* __restrict__ res, const float* __restrict__ z,
                        float* __restrict__ out,
                        const float* __restrict__ gamma, const float* __restrict__ beta){
  size_t i4 = (size_t)blockIdx.x*256 + threadIdx.x;
  int c = (int)((i4 >> 4) & 127);
  float mu  = g_sum[c] * (1.0f/CNTf);
  float var = g_sq[c]  * (1.0f/CNTf) - mu*mu;
  float sc  = gamma[c] * rsqrtf(var + EPSf);
  float sh  = beta[c] - mu*sc;
  float4 zr = ((const float4*)z)[i4];
  float4 rr = ((const float4*)res)[i4];
  float4 o;
  o.x = lrelu(rr.x + zr.x*sc + sh);
  o.y = lrelu(rr.y + zr.y*sc + sh);
  o.z = lrelu(rr.z + zr.z*sc + sh);
  o.w = lrelu(rr.w + zr.w*sc + sh);
  ((float4*)out)[i4] = o;
}

__global__ void k_zero(){
  int i = threadIdx.x;
  if (i < Cd){ g_sum[i] = 0.f; g_sq[i] = 0.f; }
}

// ---------------------------------------------------------------------------
extern "C" void kernel_launch(void* const* d_in, const int* in_sizes, int n_in,
                              void* d_out, int out_size){
  const float* x     = (const float*)d_in[0];
  const float* att1  = (const float*)d_in[1];
  const float* att2  = (const float*)d_in[2];
  const float* alpt  = (const float*)d_in[3];
  const float* w_in  = (const float*)d_in[4];
  const float* b_in  = (const float*)d_in[5];
  const float* w_out = (const float*)d_in[6];
  const float* b_out = (const float*)d_in[7];
  const float* g_o   = (const float*)d_in[8];
  const float* be_o  = (const float*)d_in[9];
  const float* w_ff  = (const float*)d_in[10];
  const float* b_ff  = (const float*)d_in[11];
  const float* g_f   = (const float*)d_in[12];
  const float* be_f  = (const float*)d_in[13];

  float *px0, *px1, *py1, *pz;
  cudaGetSymbolAddress((void**)&px0, g_x0);
  cudaGetSymbolAddress((void**)&px1, g_x1);
  cudaGetSymbolAddress((void**)&py1, g_y1);
  cudaGetSymbolAddress((void**)&pz,  g_z);

  const int SM_QK = (8704 + 192*136)*2;   // 69632 B
  const int SM_AV = (22528 + 128*136)*2;  // 79872 B
  const int SM_FF = (8704 + 128*136)*2;   // 52224 B
  cudaFuncSetAttribute(k_qk, cudaFuncAttributeMaxDynamicSharedMemorySize, SM_QK);
  cudaFuncSetAttribute(k_av, cudaFuncAttributeMaxDynamicSharedMemorySize, SM_AV);
  cudaFuncSetAttribute(k_ff, cudaFuncAttributeMaxDynamicSharedMemorySize, SM_FF);

  k_tin<<<dim3(256,192), dim3(32,8)>>>(x);

  auto run_block = [&](const float* attb, const float* inb, float* outb){
    k_qk <<<NPVd,256,SM_QK>>>(inb, w_in, b_in);
    k_att<<<NN*Sd*PPd,256>>>(attb, alpt);
    k_zero<<<1,128>>>();
    k_av <<<NPVd,256,SM_AV>>>(inb, w_out, b_out);
    k_bnres<<<TOTd/4/256,256>>>(inb, pz, py1, g_o, be_o);
    k_zero<<<1,128>>>();
    k_ff <<<NPVd,256,SM_FF>>>(py1, w_ff, b_ff);
    k_bnres<<<TOTd/4/256,256>>>(py1, pz, outb, g_f, be_f);
  };

  run_block(att1, px0, px1);
  run_block(att2, px1, px0);

  k_tout<<<dim3(256,192), dim3(32,8)>>>(px0, (float*)d_out);
}

// round 11
// speedup vs baseline: 1.5566x; 1.0995x over previous
#include <cuda_runtime.h>
#include <cuda_fp16.h>
#include <math.h>
#include <stdint.h>

#define NN  32
#define PPd 6
#define Cd  128
#define Td  64
#define Vd  25
#define Sd  3
#define CId 32
#define NPd   (NN*PPd)
#define NPVd  (NPd*Vd)        // 4800
#define SLAB  (Cd*Td)         // 8192
#define QKOd  (2*Sd*CId)      // 192
#define TOTd  (NPVd*SLAB)
#define CNTf  307200.0f
#define EPSf  1e-5f
#define NEGf  0.1f

__device__ float  g_x0[TOTd];
__device__ float  g_x1[TOTd];
__device__ float  g_y1[TOTd];
__device__ __half g_z16[TOTd];
__device__ __half g_qk16[NPVd*QKOd*Td];     // [npv][o=192][t=64] fp16
__device__ float  g_att[NN*Sd*PPd*Td*Td];
__device__ float  g_sum[512];               // 4 buffers of 128
__device__ float  g_sq [512];

__device__ __forceinline__ float lrelu(float x){ return x >= 0.f ? x : NEGf*x; }

__device__ __forceinline__ uint2 pack4(float4 v){
  __half2 h0 = __floats2half2_rn(v.x, v.y);
  __half2 h1 = __floats2half2_rn(v.z, v.w);
  uint2 u; u.x = *(uint32_t*)&h0; u.y = *(uint32_t*)&h1; return u;
}
// m16n8k16 fp16 MMA, fp32 accumulate
__device__ __forceinline__ void mmah(float c[4], const uint32_t a[4], const uint32_t b[2]){
  asm volatile(
    "mma.sync.aligned.m16n8k16.row.col.f32.f16.f16.f32 "
    "{%0,%1,%2,%3},{%4,%5,%6,%7},{%8,%9},{%0,%1,%2,%3};\n"
    : "+f"(c[0]),"+f"(c[1]),"+f"(c[2]),"+f"(c[3])
    : "r"(a[0]),"r"(a[1]),"r"(a[2]),"r"(a[3]),"r"(b[0]),"r"(b[1]));
}
#define LDU32(p) (*(const uint32_t*)(p))

// ---------------------------------------------------------------------------
// Input transpose: x[(n,p)][c][t][v] -> g_x0[(n,p)][v][c][t]
__global__ void k_tin(const float* __restrict__ x){
  __shared__ float tile[32][33];
  int np = blockIdx.y, m0 = blockIdx.x*32;
  const float* src = x + (size_t)np*(Cd*Td*Vd);
  float* dst = g_x0 + (size_t)np*(Vd*SLAB);
  int tx = threadIdx.x, ty = threadIdx.y;
  #pragma unroll
  for (int k=0;k<4;k++){ int m = m0 + ty + k*8; if (tx < Vd) tile[ty+k*8][tx] = src[(size_t)m*Vd + tx]; }
  __syncthreads();
  #pragma unroll
  for (int k=0;k<4;k++){ int v = ty + k*8; if (v < Vd) dst[(size_t)v*SLAB + m0 + tx] = tile[tx][v]; }
}
__global__ void k_tout(const float* __restrict__ srcb, float* __restrict__ dst){
  __shared__ float tile[32][33];
  int np = blockIdx.y, m0 = blockIdx.x*32;
  const float* src = srcb + (size_t)np*(Vd*SLAB);
  float* d = dst + (size_t)np*(Cd*Td*Vd);
  int tx = threadIdx.x, ty = threadIdx.y;
  #pragma unroll
  for (int k=0;k<4;k++){ int v = ty + k*8; if (v < Vd) tile[v][tx] = src[(size_t)v*SLAB + m0 + tx]; }
  __syncthreads();
  #pragma unroll
  for (int k=0;k<4;k++){ int m = m0 + ty + k*8; if (tx < Vd) d[(size_t)m*Vd + tx] = tile[tx][ty + k*8]; }
}

// ---------------------------------------------------------------------------
// QK conv (fp16 mma): per npv  Out[192x64] = W_in[192x128] * X[128x64] + b
// output stored fp16 to g_qk16 [o][t].
__global__ void __launch_bounds__(256,2) k_qk(const float* __restrict__ in,
                                              const float* __restrict__ w_in,
                                              const float* __restrict__ b_in){
  extern __shared__ __half smh[];
  __half* Xt = smh;           // [t=64][c=128] stride 136
  __half* Wc = smh + 8704;    // [o=192][c=128] stride 136
  int npv = blockIdx.x;
  int tid = threadIdx.x, lane = tid&31, w = tid>>5;
  int m0 = (w&3)*48, n0 = (w>>2)*32;
  int gid = lane>>2, tig = lane&3;

  const float4* xin4 = (const float4*)(in + (size_t)npv*SLAB);
  for (int i=tid;i<2048;i+=256){
    int c = i>>4, t0 = (i&15)<<2; float4 v = xin4[i];
    Xt[(t0  )*136+c] = __float2half_rn(v.x);
    Xt[(t0+1)*136+c] = __float2half_rn(v.y);
    Xt[(t0+2)*136+c] = __float2half_rn(v.z);
    Xt[(t0+3)*136+c] = __float2half_rn(v.w);
  }
  for (int i=tid;i<192*32;i+=256){
    int o = i>>5, c0 = (i&31)<<2;
    *(uint2*)&Wc[o*136 + c0] = pack4(*(const float4*)&w_in[o*128 + c0]);
  }
  __syncthreads();

  float acc[3][4][4];
  #pragma unroll
  for (int mf=0;mf<3;mf++)
    #pragma unroll
    for (int nf=0;nf<4;nf++){ acc[mf][nf][0]=acc[mf][nf][1]=acc[mf][nf][2]=acc[mf][nf][3]=0.f; }

  #pragma unroll
  for (int ks=0;ks<8;ks++){
    int kk = ks*16 + 2*tig;
    uint32_t a[3][4], b[4][2];
    #pragma unroll
    for (int mf=0;mf<3;mf++){
      int r = m0 + mf*16 + gid;
      a[mf][0] = LDU32(&Wc[r*136 + kk]);
      a[mf][1] = LDU32(&Wc[(r+8)*136 + kk]);
      a[mf][2] = LDU32(&Wc[r*136 + kk + 8]);
      a[mf][3] = LDU32(&Wc[(r+8)*136 + kk + 8]);
    }
    #pragma unroll
    for (int nf=0;nf<4;nf++){
      int col = n0 + nf*8 + gid;
      b[nf][0] = LDU32(&Xt[col*136 + kk]);
      b[nf][1] = LDU32(&Xt[col*136 + kk + 8]);
    }
    #pragma unroll
    for (int mf=0;mf<3;mf++)
      #pragma unroll
      for (int nf=0;nf<4;nf++) mmah(acc[mf][nf], a[mf], b[nf]);
  }
  __half* outp = g_qk16 + (size_t)npv*QKOd*Td;
  #pragma unroll
  for (int mf=0;mf<3;mf++){
    int r = m0 + mf*16 + gid;
    float b0 = b_in[r], b1 = b_in[r+8];
    #pragma unroll
    for (int nf=0;nf<4;nf++){
      int col = n0 + nf*8 + 2*tig;
      *(__half2*)&outp[r*64 + col]     = __floats2half2_rn(acc[mf][nf][0]+b0, acc[mf][nf][1]+b0);
      *(__half2*)&outp[(r+8)*64 + col] = __floats2half2_rn(acc[mf][nf][2]+b1, acc[mf][nf][3]+b1);
    }
  }
}

// ---------------------------------------------------------------------------
// Attention scores (fp16 mma): per (n,s,p): 64x64 over K=(c=32)x(v=25)=800
__global__ void __launch_bounds__(256) k_att(const float* __restrict__ attb,
                                             const float* __restrict__ alphat){
  __shared__ __half Qs[64*40];   // [t][c] stride 40
  __shared__ __half Ks[64*40];   // [q][c] stride 40
  int b = blockIdx.x;
  int p = b % PPd; int s = (b/PPd) % Sd; int n = b/(PPd*Sd);
  int np = n*PPd + p;
  int tid = threadIdx.x, lane = tid&31, w = tid>>5;
  int m0 = (w&3)*16, n0 = (w>>2)*32;
  int gid = lane>>2, tig = lane&3;

  float acc[4][4];
  #pragma unroll
  for (int nf=0;nf<4;nf++){ acc[nf][0]=acc[nf][1]=acc[nf][2]=acc[nf][3]=0.f; }

  for (int v=0; v<Vd; v++){
    const __half* base = g_qk16 + ((size_t)(np*Vd + v))*QKOd*Td;
    const __half* qb = base + (size_t)(s*CId)*Td;           // [32 c][64 t]
    const __half* kb = base + (size_t)(Sd*CId + s*CId)*Td;
    __syncthreads();
    // transpose-stage: smem[t][c] from gmem[c][t]
    for (int i=tid; i<512; i+=256){
      int c = i>>4, t0 = (i&15)<<2;
      uint2 uq = *(const uint2*)&qb[c*64 + t0];
      uint2 uk = *(const uint2*)&kb[c*64 + t0];
      __half2 q0 = *(__half2*)&uq.x, q1 = *(__half2*)&uq.y;
      __half2 k0 = *(__half2*)&uk.x, k1 = *(__half2*)&uk.y;
      Qs[(t0  )*40+c] = __low2half(q0);  Qs[(t0+1)*40+c] = __high2half(q0);
      Qs[(t0+2)*40+c] = __low2half(q1);  Qs[(t0+3)*40+c] = __high2half(q1);
      Ks[(t0  )*40+c] = __low2half(k0);  Ks[(t0+1)*40+c] = __high2half(k0);
      Ks[(t0+2)*40+c] = __low2half(k1);  Ks[(t0+3)*40+c] = __high2half(k1);
    }
    __syncthreads();
    #pragma unroll
    for (int ks=0;ks<2;ks++){
      int kk = ks*16 + 2*tig;
      uint32_t a[4], bb[4][2];
      int r = m0 + gid;
      a[0] = LDU32(&Qs[r*40 + kk]);
      a[1] = LDU32(&Qs[(r+8)*40 + kk]);
      a[2] = LDU32(&Qs[r*40 + kk + 8]);
      a[3] = LDU32(&Qs[(r+8)*40 + kk + 8]);
      #pragma unroll
      for (int nf=0;nf<4;nf++){
        int col = n0 + nf*8 + gid;
        bb[nf][0] = LDU32(&Ks[col*40 + kk]);
        bb[nf][1] = LDU32(&Ks[col*40 + kk + 8]);
      }
      #pragma unroll
      for (int nf=0;nf<4;nf++) mmah(acc[nf], a, bb[nf]);
    }
  }
  float al = alphat[s];
  float* attp = g_att + (size_t)b*Td*Td;
  const float* bp = attb + (size_t)s*Td*Td;
  #pragma unroll
  for (int nf=0;nf<4;nf++){
    int t = m0 + gid, q = n0 + nf*8 + 2*tig;
    *(float2*)&attp[t*Td+q] = make_float2(
      bp[t*Td+q]   + tanhf(acc[nf][0]*(1.f/800.f))*al,
      bp[t*Td+q+1] + tanhf(acc[nf][1]*(1.f/800.f))*al);
    *(float2*)&attp[(t+8)*Td+q] = make_float2(
      bp[(t+8)*Td+q]   + tanhf(acc[nf][2]*(1.f/800.f))*al,
      bp[(t+8)*Td+q+1] + tanhf(acc[nf][3]*(1.f/800.f))*al);
  }
}

// ---------------------------------------------------------------------------
// Fused att-apply + S*C->C conv + BN stats (fp16 mma).
__global__ void __launch_bounds__(256,2) k_av(const float* __restrict__ in,
                                              const float* __restrict__ w_out,
                                              const float* __restrict__ b_out,
                                              int sbuf){
  extern __shared__ __half smh[];
  __half* Xa   = smh;           // [c=128][t=64]  stride 72
  __half* attT = smh + 9216;    // [q=64][t=64]   stride 72
  __half* Yt   = smh + 13824;   // [q=64][c=128]  stride 136
  __half* Wc   = smh + 22528;   // [o=128][c=128] stride 136
  int npv = blockIdx.x;
  int np = npv / Vd;
  int p = np % PPd, n = np / PPd;
  int tid = threadIdx.x, lane = tid&31, w = tid>>5;
  int m0 = (w&3)*32, n0 = (w>>2)*32;
  int gid = lane>>2, tig = lane&3;

  const float4* xin4 = (const float4*)(in + (size_t)npv*SLAB);
  for (int i=tid;i<2048;i+=256){
    int c = i>>4, t0 = (i&15)<<2;
    *(uint2*)&Xa[c*72 + t0] = pack4(xin4[i]);
  }
  float zacc[2][4][4];
  #pragma unroll
  for (int mf=0;mf<2;mf++)
    #pragma unroll
    for (int nf=0;nf<4;nf++){ zacc[mf][nf][0]=zacc[mf][nf][1]=zacc[mf][nf][2]=zacc[mf][nf][3]=0.f; }

  for (int s=0;s<Sd;s++){
    __syncthreads();
    const float4* a4 = (const float4*)(g_att + ((size_t)((n*Sd+s)*PPd+p))*Td*Td);
    for (int i=tid;i<1024;i+=256){
      int t = i>>4, q0 = (i&15)<<2; float4 v = a4[i];
      attT[(q0  )*72+t] = __float2half_rn(v.x);
      attT[(q0+1)*72+t] = __float2half_rn(v.y);
      attT[(q0+2)*72+t] = __float2half_rn(v.z);
      attT[(q0+3)*72+t] = __float2half_rn(v.w);
    }
    for (int i=tid;i<128*32;i+=256){
      int o = i>>5, c0 = (i&31)<<2;
      *(uint2*)&Wc[o*136 + c0] = pack4(*(const float4*)&w_out[(size_t)o*(Sd*Cd) + s*Cd + c0]);
    }
    __syncthreads();

    // Stage 1: Y = Xa * attT
    float yacc[2][4][4];
    #pragma unroll
    for (int mf=0;mf<2;mf++)
      #pragma unroll
      for (int nf=0;nf<4;nf++){ yacc[mf][nf][0]=yacc[mf][nf][1]=yacc[mf][nf][2]=yacc[mf][nf][3]=0.f; }
    #pragma unroll
    for (int ks=0;ks<4;ks++){
      int kk = ks*16 + 2*tig;
      uint32_t a[2][4], b[4][2];
      #pragma unroll
      for (int mf=0;mf<2;mf++){
        int r = m0 + mf*16 + gid;
        a[mf][0] = LDU32(&Xa[r*72 + kk]);
        a[mf][1] = LDU32(&Xa[(r+8)*72 + kk]);
        a[mf][2] = LDU32(&Xa[r*72 + kk + 8]);
        a[mf][3] = LDU32(&Xa[(r+8)*72 + kk + 8]);
      }
      #pragma unroll
      for (int nf=0;nf<4;nf++){
        int col = n0 + nf*8 + gid;
        b[nf][0] = LDU32(&attT[col*72 + kk]);
        b[nf][1] = LDU32(&attT[col*72 + kk + 8]);
      }
      #pragma unroll
      for (int mf=0;mf<2;mf++)
        #pragma unroll
        for (int nf=0;nf<4;nf++) mmah(yacc[mf][nf], a[mf], b[nf]);
    }
    #pragma unroll
    for (int mf=0;mf<2;mf++){
      int c = m0 + mf*16 + gid;
      #pragma unroll
      for (int nf=0;nf<4;nf++){
        int q = n0 + nf*8 + 2*tig;
        Yt[q*136 + c]       = __float2half_rn(yacc[mf][nf][0]);
        Yt[(q+1)*136 + c]   = __float2half_rn(yacc[mf][nf][1]);
        Yt[q*136 + c + 8]   = __float2half_rn(yacc[mf][nf][2]);
        Yt[(q+1)*136 + c+8] = __float2half_rn(yacc[mf][nf][3]);
      }
    }
    __syncthreads();

    // Stage 2: Z += Wc * Yt
    #pragma unroll
    for (int ks=0;ks<8;ks++){
      int kk = ks*16 + 2*tig;
      uint32_t a[2][4], b[4][2];
      #pragma unroll
      for (int mf=0;mf<2;mf++){
        int r = m0 + mf*16 + gid;
        a[mf][0] = LDU32(&Wc[r*136 + kk]);
        a[mf][1] = LDU32(&Wc[(r+8)*136 + kk]);
        a[mf][2] = LDU32(&Wc[r*136 + kk + 8]);
        a[mf][3] = LDU32(&Wc[(r+8)*136 + kk + 8]);
      }
      #pragma unroll
      for (int nf=0;nf<4;nf++){
        int col = n0 + nf*8 + gid;
        b[nf][0] = LDU32(&Yt[col*136 + kk]);
        b[nf][1] = LDU32(&Yt[col*136 + kk + 8]);
      }
      #pragma unroll
      for (int mf=0;mf<2;mf++)
        #pragma unroll
        for (int nf=0;nf<4;nf++) mmah(zacc[mf][nf], a[mf], b[nf]);
    }
  }

  __half* zp = g_z16 + (size_t)npv*SLAB;
  #pragma unroll
  for (int mf=0;mf<2;mf++){
    int r = m0 + mf*16 + gid;
    float bo0 = b_out[r], bo1 = b_out[r+8];
    float s0a=0.f, s0b=0.f, s1a=0.f, s1b=0.f;
    #pragma unroll
    for (int nf=0;nf<4;nf++){
      int col = n0 + nf*8 + 2*tig;
      float z00 = zacc[mf][nf][0]+bo0, z01 = zacc[mf][nf][1]+bo0;
      float z10 = zacc[mf][nf][2]+bo1, z11 = zacc[mf][nf][3]+bo1;
      *(__half2*)&zp[r*64 + col]     = __floats2half2_rn(z00, z01);
      *(__half2*)&zp[(r+8)*64 + col] = __floats2half2_rn(z10, z11);
      s0a += z00+z01; s0b += z00*z00+z01*z01;
      s1a += z10+z11; s1b += z10*z10+z11*z11;
    }
    #pragma unroll
    for (int off=1; off<4; off<<=1){
      s0a += __shfl_xor_sync(0xffffffffu, s0a, off);
      s0b += __shfl_xor_sync(0xffffffffu, s0b, off);
      s1a += __shfl_xor_sync(0xffffffffu, s1a, off);
      s1b += __shfl_xor_sync(0xffffffffu, s1b, off);
    }
    if (tig==0){
      atomicAdd(&g_sum[sbuf+r], s0a);   atomicAdd(&g_sq[sbuf+r], s0b);
      atomicAdd(&g_sum[sbuf+r+8], s1a); atomicAdd(&g_sq[sbuf+r+8], s1b);
    }
  }
}

// ---------------------------------------------------------------------------
// FF conv (fp16 mma)
__global__ void __launch_bounds__(256,2) k_ff(const float* __restrict__ in,
                                              const float* __restrict__ w_ff,
                                              const float* __restrict__ b_ff,
                                              int sbuf){
  extern __shared__ __half smh[];
  __half* Xt = smh;           // [t=64][c=128] stride 136
  __half* Wc = smh + 8704;    // [o=128][c=128] stride 136
  int npv = blockIdx.x;
  int tid = threadIdx.x, lane = tid&31, w = tid>>5;
  int m0 = (w&3)*32, n0 = (w>>2)*32;
  int gid = lane>>2, tig = lane&3;

  const float4* xin4 = (const float4*)(in + (size_t)npv*SLAB);
  for (int i=tid;i<2048;i+=256){
    int c = i>>4, t0 = (i&15)<<2; float4 v = xin4[i];
    Xt[(t0  )*136+c] = __float2half_rn(v.x);
    Xt[(t0+1)*136+c] = __float2half_rn(v.y);
    Xt[(t0+2)*136+c] = __float2half_rn(v.z);
    Xt[(t0+3)*136+c] = __float2half_rn(v.w);
  }
  for (int i=tid;i<128*32;i+=256){
    int o = i>>5, c0 = (i&31)<<2;
    *(uint2*)&Wc[o*136 + c0] = pack4(*(const float4*)&w_ff[o*128 + c0]);
  }
  __syncthreads();

  float acc[2][4][4];
  #pragma unroll
  for (int mf=0;mf<2;mf++)
    #pragma unroll
    for (int nf=0;nf<4;nf++){ acc[mf][nf][0]=acc[mf][nf][1]=acc[mf][nf][2]=acc[mf][nf][3]=0.f; }

  #pragma unroll
  for (int ks=0;ks<8;ks++){
    int kk = ks*16 + 2*tig;
    uint32_t a[2][4], b[4][2];
    #pragma unroll
    for (int mf=0;mf<2;mf++){
      int r = m0 + mf*16 + gid;
      a[mf][0] = LDU32(&Wc[r*136 + kk]);
      a[mf][1] = LDU32(&Wc[(r+8)*136 + kk]);
      a[mf][2] = LDU32(&Wc[r*136 + kk + 8]);
      a[mf][3] = LDU32(&Wc[(r+8)*136 + kk + 8]);
    }
    #pragma unroll
    for (int nf=0;nf<4;nf++){
      int col = n0 + nf*8 + gid;
      b[nf][0] = LDU32(&Xt[col*136 + kk]);
      b[nf][1] = LDU32(&Xt[col*136 + kk + 8]);
    }
    #pragma unroll
    for (int mf=0;mf<2;mf++)
      #pragma unroll
      for (int nf=0;nf<4;nf++) mmah(acc[mf][nf], a[mf], b[nf]);
  }
  __half* zp = g_z16 + (size_t)npv*SLAB;
  #pragma unroll
  for (int mf=0;mf<2;mf++){
    int r = m0 + mf*16 + gid;
    float bo0 = b_ff[r], bo1 = b_ff[r+8];
    float s0a=0.f, s0b=0.f, s1a=0.f, s1b=0.f;
    #pragma unroll
    for (int nf=0;nf<4;nf++){
      int col = n0 + nf*8 + 2*tig;
      float z00 = acc[mf][nf][0]+bo0, z01 = acc[mf][nf][1]+bo0;
      float z10 = acc[mf][nf][2]+bo1, z11 = acc[mf][nf][3]+bo1;
      *(__half2*)&zp[r*64 + col]     = __floats2half2_rn(z00, z01);
      *(__half2*)&zp[(r+8)*64 + col] = __floats2half2_rn(z10, z11);
      s0a += z00+z01; s0b += z00*z00+z01*z01;
      s1a += z10+z11; s1b += z10*z10+z11*z11;
    }
    #pragma unroll
    for (int off=1; off<4; off<<=1){
      s0a += __shfl_xor_sync(0xffffffffu, s0a, off);
      s0b += __shfl_xor_sync(0xffffffffu, s0b, off);
      s1a += __shfl_xor_sync(0xffffffffu, s1a, off);
      s1b += __shfl_xor_sync(0xffffffffu, s1b, off);
    }
    if (tig==0){
      atomicAdd(&g_sum[sbuf+r], s0a);   atomicAdd(&g_sq[sbuf+r], s0b);
      atomicAdd(&g_sum[sbuf+r+8], s1a); atomicAdd(&g_sq[sbuf+r+8], s1b);
    }
  }
}

// ---------------------------------------------------------------------------
// BN apply + residual + leaky (z in fp16)
__global__ void k_bnres(const float* __restrict__ res, const __half* __restrict__ z,
                        float* __restrict__ out,
                        const float* __restrict__ gamma, const float* __restrict__ beta,
                        int sbuf){
  size_t i4 = (size_t)blockIdx.x*256 + threadIdx.x;
  int c = (int)((i4 >> 4) & 127);
  float mu  = g_sum[sbuf+c] * (1.0f/CNTf);
  float var = g_sq[sbuf+c]  * (1.0f/CNTf) - mu*mu;
  float sc  = gamma[c] * rsqrtf(var + EPSf);
  float sh  = beta[c] - mu*sc;
  uint2 zu = ((const uint2*)z)[i4];
  __half2 za = *(__half2*)&zu.x, zb = *(__half2*)&zu.y;
  float4 rr = ((const float4*)res)[i4];
  float4 o;
  o.x = lrelu(rr.x + __low2float(za)*sc + sh);
  o.y = lrelu(rr.y + __high2float(za)*sc + sh);
  o.z = lrelu(rr.z + __low2float(zb)*sc + sh);
  o.w = lrelu(rr.w + __high2float(zb)*sc + sh);
  ((float4*)out)[i4] = o;
}

__global__ void k_zero(){
  int i = blockIdx.x*256 + threadIdx.x;
  if (i < 512){ g_sum[i] = 0.f; g_sq[i] = 0.f; }
}

// ---------------------------------------------------------------------------
extern "C" void kernel_launch(void* const* d_in, const int* in_sizes, int n_in,
                              void* d_out, int out_size){
  const float* x     = (const float*)d_in[0];
  const float* att1  = (const float*)d_in[1];
  const float* att2  = (const float*)d_in[2];
  const float* alpt  = (const float*)d_in[3];
  const float* w_in  = (const float*)d_in[4];
  const float* b_in  = (const float*)d_in[5];
  const float* w_out = (const float*)d_in[6];
  const float* b_out = (const float*)d_in[7];
  const float* g_o   = (const float*)d_in[8];
  const float* be_o  = (const float*)d_in[9];
  const float* w_ff  = (const float*)d_in[10];
  const float* b_ff  = (const float*)d_in[11];
  const float* g_f   = (const float*)d_in[12];
  const float* be_f  = (const float*)d_in[13];

  float *px0, *px1, *py1;
  __half *pz;
  cudaGetSymbolAddress((void**)&px0, g_x0);
  cudaGetSymbolAddress((void**)&px1, g_x1);
  cudaGetSymbolAddress((void**)&py1, g_y1);
  cudaGetSymbolAddress((void**)&pz,  g_z16);

  const int SM_QK = (8704 + 192*136)*2;   // 69632 B
  const int SM_AV = (22528 + 128*136)*2;  // 79872 B
  const int SM_FF = (8704 + 128*136)*2;   // 52224 B
  cudaFuncSetAttribute(k_qk, cudaFuncAttributeMaxDynamicSharedMemorySize, SM_QK);
  cudaFuncSetAttribute(k_av, cudaFuncAttributeMaxDynamicSharedMemorySize, SM_AV);
  cudaFuncSetAttribute(k_ff, cudaFuncAttributeMaxDynamicSharedMemorySize, SM_FF);

  k_zero<<<2,256>>>();
  k_tin<<<dim3(256,192), dim3(32,8)>>>(x);

  auto run_block = [&](const float* attb, const float* inb, float* outb, int sb){
    k_qk <<<NPVd,256,SM_QK>>>(inb, w_in, b_in);
    k_att<<<NN*Sd*PPd,256>>>(attb, alpt);
    k_av <<<NPVd,256,SM_AV>>>(inb, w_out, b_out, sb*128);
    k_bnres<<<TOTd/4/256,256>>>(inb, pz, py1, g_o, be_o, sb*128);
    k_ff <<<NPVd,256,SM_FF>>>(py1, w_ff, b_ff, (sb+1)*128);
    k_bnres<<<TOTd/4/256,256>>>(py1, pz, outb, g_f, be_f, (sb+1)*128);
  };

  run_block(att1, px0, px1, 0);
  run_block(att2, px1, px0, 2);

  k_tout<<<dim3(256,192), dim3(32,8)>>>(px0, (float*)d_out);
}

// round 13
// speedup vs baseline: 1.6579x; 1.0651x over previous
#include <cuda_runtime.h>
#include <cuda_fp16.h>
#include <math.h>
#include <stdint.h>

#define NN  32
#define PPd 6
#define Cd  128
#define Td  64
#define Vd  25
#define Sd  3
#define CId 32
#define NPd   (NN*PPd)
#define NPVd  (NPd*Vd)        // 4800
#define SLAB  (Cd*Td)         // 8192
#define QKOd  (2*Sd*CId)      // 192
#define TOTd  (NPVd*SLAB)
#define CNTf  307200.0f
#define EPSf  1e-5f
#define NEGf  0.1f

__device__ float  g_x0[TOTd];
__device__ float  g_x1[TOTd];
__device__ __half g_x0h[TOTd];
__device__ __half g_x1h[TOTd];
__device__ __half g_z1[TOTd];
__device__ __half g_z2[TOTd];
__device__ __half g_qk16[NPVd*QKOd*Td];     // [npv][o=192][t=64] fp16
__device__ float  g_att[NN*Sd*PPd*Td*Td];
__device__ float  g_sum[512];               // 4 buffers of 128
__device__ float  g_sq [512];

__device__ __forceinline__ float lrelu(float x){ return x >= 0.f ? x : NEGf*x; }

__device__ __forceinline__ uint2 pack4(float4 v){
  __half2 h0 = __floats2half2_rn(v.x, v.y);
  __half2 h1 = __floats2half2_rn(v.z, v.w);
  uint2 u; u.x = *(uint32_t*)&h0; u.y = *(uint32_t*)&h1; return u;
}
// m16n8k16 fp16 MMA, fp32 accumulate
__device__ __forceinline__ void mmah(float c[4], const uint32_t a[4], const uint32_t b[2]){
  asm volatile(
    "mma.sync.aligned.m16n8k16.row.col.f32.f16.f16.f32 "
    "{%0,%1,%2,%3},{%4,%5,%6,%7},{%8,%9},{%0,%1,%2,%3};\n"
    : "+f"(c[0]),"+f"(c[1]),"+f"(c[2]),"+f"(c[3])
    : "r"(a[0]),"r"(a[1]),"r"(a[2]),"r"(a[3]),"r"(b[0]),"r"(b[1]));
}
#define LDU32(p) (*(const uint32_t*)(p))

// ---------------------------------------------------------------------------
// Input transpose: x[(n,p)][c][t][v] -> g_x0[(n,p)][v][c][t] (fp32 + fp16)
__global__ void k_tin(const float* __restrict__ x){
  __shared__ float tile[32][33];
  int np = blockIdx.y, m0 = blockIdx.x*32;
  const float* src = x + (size_t)np*(Cd*Td*Vd);
  float*  dst  = g_x0  + (size_t)np*(Vd*SLAB);
  __half* dsth = g_x0h + (size_t)np*(Vd*SLAB);
  int tx = threadIdx.x, ty = threadIdx.y;
  #pragma unroll
  for (int k=0;k<4;k++){ int m = m0 + ty + k*8; if (tx < Vd) tile[ty+k*8][tx] = src[(size_t)m*Vd + tx]; }
  __syncthreads();
  #pragma unroll
  for (int k=0;k<4;k++){
    int v = ty + k*8;
    if (v < Vd){
      float val = tile[tx][v];
      dst [(size_t)v*SLAB + m0 + tx] = val;
      dsth[(size_t)v*SLAB + m0 + tx] = __float2half_rn(val);
    }
  }
}
__global__ void k_tout(const float* __restrict__ srcb, float* __restrict__ dst){
  __shared__ float tile[32][33];
  int np = blockIdx.y, m0 = blockIdx.x*32;
  const float* src = srcb + (size_t)np*(Vd*SLAB);
  float* d = dst + (size_t)np*(Cd*Td*Vd);
  int tx = threadIdx.x, ty = threadIdx.y;
  #pragma unroll
  for (int k=0;k<4;k++){ int v = ty + k*8; if (v < Vd) tile[v][tx] = src[(size_t)v*SLAB + m0 + tx]; }
  __syncthreads();
  #pragma unroll
  for (int k=0;k<4;k++){ int m = m0 + ty + k*8; if (tx < Vd) d[(size_t)m*Vd + tx] = tile[tx][ty + k*8]; }
}

// ---------------------------------------------------------------------------
// QK conv (fp16 mma): per npv  Out[192x64] = W_in[192x128] * X[128x64] + b
__global__ void __launch_bounds__(256,2) k_qk(const __half* __restrict__ in16,
                                              const float* __restrict__ w_in,
                                              const float* __restrict__ b_in){
  extern __shared__ __half smh[];
  __half* Xt = smh;           // [t=64][c=128] stride 136
  __half* Wc = smh + 8704;    // [o=192][c=128] stride 136
  int npv = blockIdx.x;
  int tid = threadIdx.x, lane = tid&31, w = tid>>5;
  int m0 = (w&3)*48, n0 = (w>>2)*32;
  int gid = lane>>2, tig = lane&3;

  const uint4* xin = (const uint4*)(in16 + (size_t)npv*SLAB);
  for (int i=tid;i<1024;i+=256){
    int c = i>>3, t0 = (i&7)<<3;
    uint4 u = xin[i];
    __half2 h01=*(__half2*)&u.x, h23=*(__half2*)&u.y, h45=*(__half2*)&u.z, h67=*(__half2*)&u.w;
    Xt[(t0+0)*136+c]=__low2half(h01); Xt[(t0+1)*136+c]=__high2half(h01);
    Xt[(t0+2)*136+c]=__low2half(h23); Xt[(t0+3)*136+c]=__high2half(h23);
    Xt[(t0+4)*136+c]=__low2half(h45); Xt[(t0+5)*136+c]=__high2half(h45);
    Xt[(t0+6)*136+c]=__low2half(h67); Xt[(t0+7)*136+c]=__high2half(h67);
  }
  for (int i=tid;i<192*32;i+=256){
    int o = i>>5, c0 = (i&31)<<2;
    *(uint2*)&Wc[o*136 + c0] = pack4(*(const float4*)&w_in[o*128 + c0]);
  }
  __syncthreads();

  float acc[3][4][4];
  #pragma unroll
  for (int mf=0;mf<3;mf++)
    #pragma unroll
    for (int nf=0;nf<4;nf++){ acc[mf][nf][0]=acc[mf][nf][1]=acc[mf][nf][2]=acc[mf][nf][3]=0.f; }

  #pragma unroll
  for (int ks=0;ks<8;ks++){
    int kk = ks*16 + 2*tig;
    uint32_t a[3][4], b[4][2];
    #pragma unroll
    for (int mf=0;mf<3;mf++){
      int r = m0 + mf*16 + gid;
      a[mf][0] = LDU32(&Wc[r*136 + kk]);
      a[mf][1] = LDU32(&Wc[(r+8)*136 + kk]);
      a[mf][2] = LDU32(&Wc[r*136 + kk + 8]);
      a[mf][3] = LDU32(&Wc[(r+8)*136 + kk + 8]);
    }
    #pragma unroll
    for (int nf=0;nf<4;nf++){
      int col = n0 + nf*8 + gid;
      b[nf][0] = LDU32(&Xt[col*136 + kk]);
      b[nf][1] = LDU32(&Xt[col*136 + kk + 8]);
    }
    #pragma unroll
    for (int mf=0;mf<3;mf++)
      #pragma unroll
      for (int nf=0;nf<4;nf++) mmah(acc[mf][nf], a[mf], b[nf]);
  }
  __half* outp = g_qk16 + (size_t)npv*QKOd*Td;
  #pragma unroll
  for (int mf=0;mf<3;mf++){
    int r = m0 + mf*16 + gid;
    float b0 = b_in[r], b1 = b_in[r+8];
    #pragma unroll
    for (int nf=0;nf<4;nf++){
      int col = n0 + nf*8 + 2*tig;
      *(__half2*)&outp[r*64 + col]     = __floats2half2_rn(acc[mf][nf][0]+b0, acc[mf][nf][1]+b0);
      *(__half2*)&outp[(r+8)*64 + col] = __floats2half2_rn(acc[mf][nf][2]+b1, acc[mf][nf][3]+b1);
    }
  }
}

// ---------------------------------------------------------------------------
// Attention scores (fp16 mma): per (n,s,p): 64x64 over K=(c=32)x(v=25)=800
__global__ void __launch_bounds__(256) k_att(const float* __restrict__ attb,
                                             const float* __restrict__ alphat){
  __shared__ __half Qs[64*40];   // [t][c] stride 40
  __shared__ __half Ks[64*40];   // [q][c] stride 40
  int b = blockIdx.x;
  int p = b % PPd; int s = (b/PPd) % Sd; int n = b/(PPd*Sd);
  int np = n*PPd + p;
  int tid = threadIdx.x, lane = tid&31, w = tid>>5;
  int m0 = (w&3)*16, n0 = (w>>2)*32;
  int gid = lane>>2, tig = lane&3;

  float acc[4][4];
  #pragma unroll
  for (int nf=0;nf<4;nf++){ acc[nf][0]=acc[nf][1]=acc[nf][2]=acc[nf][3]=0.f; }

  for (int v=0; v<Vd; v++){
    const __half* base = g_qk16 + ((size_t)(np*Vd + v))*QKOd*Td;
    const __half* qb = base + (size_t)(s*CId)*Td;           // [32 c][64 t]
    const __half* kb = base + (size_t)(Sd*CId + s*CId)*Td;
    __syncthreads();
    for (int i=tid; i<512; i+=256){
      int c = i>>4, t0 = (i&15)<<2;
      uint2 uq = *(const uint2*)&qb[c*64 + t0];
      uint2 uk = *(const uint2*)&kb[c*64 + t0];
      __half2 q0 = *(__half2*)&uq.x, q1 = *(__half2*)&uq.y;
      __half2 k0 = *(__half2*)&uk.x, k1 = *(__half2*)&uk.y;
      Qs[(t0  )*40+c] = __low2half(q0);  Qs[(t0+1)*40+c] = __high2half(q0);
      Qs[(t0+2)*40+c] = __low2half(q1);  Qs[(t0+3)*40+c] = __high2half(q1);
      Ks[(t0  )*40+c] = __low2half(k0);  Ks[(t0+1)*40+c] = __high2half(k0);
      Ks[(t0+2)*40+c] = __low2half(k1);  Ks[(t0+3)*40+c] = __high2half(k1);
    }
    __syncthreads();
    #pragma unroll
    for (int ks=0;ks<2;ks++){
      int kk = ks*16 + 2*tig;
      uint32_t a[4], bb[4][2];
      int r = m0 + gid;
      a[0] = LDU32(&Qs[r*40 + kk]);
      a[1] = LDU32(&Qs[(r+8)*40 + kk]);
      a[2] = LDU32(&Qs[r*40 + kk + 8]);
      a[3] = LDU32(&Qs[(r+8)*40 + kk + 8]);
      #pragma unroll
      for (int nf=0;nf<4;nf++){
        int col = n0 + nf*8 + gid;
        bb[nf][0] = LDU32(&Ks[col*40 + kk]);
        bb[nf][1] = LDU32(&Ks[col*40 + kk + 8]);
      }
      #pragma unroll
      for (int nf=0;nf<4;nf++) mmah(acc[nf], a, bb[nf]);
    }
  }
  float al = alphat[s];
  float* attp = g_att + (size_t)b*Td*Td;
  const float* bp = attb + (size_t)s*Td*Td;
  #pragma unroll
  for (int nf=0;nf<4;nf++){
    int t = m0 + gid, q = n0 + nf*8 + 2*tig;
    *(float2*)&attp[t*Td+q] = make_float2(
      bp[t*Td+q]   + tanhf(acc[nf][0]*(1.f/800.f))*al,
      bp[t*Td+q+1] + tanhf(acc[nf][1]*(1.f/800.f))*al);
    *(float2*)&attp[(t+8)*Td+q] = make_float2(
      bp[(t+8)*Td+q]   + tanhf(acc[nf][2]*(1.f/800.f))*al,
      bp[(t+8)*Td+q+1] + tanhf(acc[nf][3]*(1.f/800.f))*al);
  }
}

// ---------------------------------------------------------------------------
// Fused att-apply + S*C->C conv + BN stats (fp16 mma). z -> g_z1
__global__ void __launch_bounds__(256,2) k_av(const __half* __restrict__ in16,
                                              const float* __restrict__ w_out,
                                              const float* __restrict__ b_out,
                                              int sbuf){
  extern __shared__ __half smh[];
  __half* Xa   = smh;           // [c=128][t=64]  stride 72
  __half* attT = smh + 9216;    // [q=64][t=64]   stride 72
  __half* Yt   = smh + 13824;   // [q=64][c=128]  stride 136
  __half* Wc   = smh + 22528;   // [o=128][c=128] stride 136
  int npv = blockIdx.x;
  int np = npv / Vd;
  int p = np % PPd, n = np / PPd;
  int tid = threadIdx.x, lane = tid&31, w = tid>>5;
  int m0 = (w&3)*32, n0 = (w>>2)*32;
  int gid = lane>>2, tig = lane&3;

  const uint4* xin = (const uint4*)(in16 + (size_t)npv*SLAB);
  for (int i=tid;i<1024;i+=256){
    int c = i>>3, t0 = (i&7)<<3;
    *(uint4*)&Xa[c*72 + t0] = xin[i];
  }
  float zacc[2][4][4];
  #pragma unroll
  for (int mf=0;mf<2;mf++)
    #pragma unroll
    for (int nf=0;nf<4;nf++){ zacc[mf][nf][0]=zacc[mf][nf][1]=zacc[mf][nf][2]=zacc[mf][nf][3]=0.f; }

  for (int s=0;s<Sd;s++){
    __syncthreads();
    const float4* a4 = (const float4*)(g_att + ((size_t)((n*Sd+s)*PPd+p))*Td*Td);
    for (int i=tid;i<1024;i+=256){
      int t = i>>4, q0 = (i&15)<<2; float4 v = a4[i];
      attT[(q0  )*72+t] = __float2half_rn(v.x);
      attT[(q0+1)*72+t] = __float2half_rn(v.y);
      attT[(q0+2)*72+t] = __float2half_rn(v.z);
      attT[(q0+3)*72+t] = __float2half_rn(v.w);
    }
    for (int i=tid;i<128*32;i+=256){
      int o = i>>5, c0 = (i&31)<<2;
      *(uint2*)&Wc[o*136 + c0] = pack4(*(const float4*)&w_out[(size_t)o*(Sd*Cd) + s*Cd + c0]);
    }
    __syncthreads();

    // Stage 1: Y = Xa * attT
    float yacc[2][4][4];
    #pragma unroll
    for (int mf=0;mf<2;mf++)
      #pragma unroll
      for (int nf=0;nf<4;nf++){ yacc[mf][nf][0]=yacc[mf][nf][1]=yacc[mf][nf][2]=yacc[mf][nf][3]=0.f; }
    #pragma unroll
    for (int ks=0;ks<4;ks++){
      int kk = ks*16 + 2*tig;
      uint32_t a[2][4], b[4][2];
      #pragma unroll
      for (int mf=0;mf<2;mf++){
        int r = m0 + mf*16 + gid;
        a[mf][0] = LDU32(&Xa[r*72 + kk]);
        a[mf][1] = LDU32(&Xa[(r+8)*72 + kk]);
        a[mf][2] = LDU32(&Xa[r*72 + kk + 8]);
        a[mf][3] = LDU32(&Xa[(r+8)*72 + kk + 8]);
      }
      #pragma unroll
      for (int nf=0;nf<4;nf++){
        int col = n0 + nf*8 + gid;
        b[nf][0] = LDU32(&attT[col*72 + kk]);
        b[nf][1] = LDU32(&attT[col*72 + kk + 8]);
      }
      #pragma unroll
      for (int mf=0;mf<2;mf++)
        #pragma unroll
        for (int nf=0;nf<4;nf++) mmah(yacc[mf][nf], a[mf], b[nf]);
    }
    #pragma unroll
    for (int mf=0;mf<2;mf++){
      int c = m0 + mf*16 + gid;
      #pragma unroll
      for (int nf=0;nf<4;nf++){
        int q = n0 + nf*8 + 2*tig;
        Yt[q*136 + c]       = __float2half_rn(yacc[mf][nf][0]);
        Yt[(q+1)*136 + c]   = __float2half_rn(yacc[mf][nf][1]);
        Yt[q*136 + c + 8]   = __float2half_rn(yacc[mf][nf][2]);
        Yt[(q+1)*136 + c+8] = __float2half_rn(yacc[mf][nf][3]);
      }
    }
    __syncthreads();

    // Stage 2: Z += Wc * Yt
    #pragma unroll
    for (int ks=0;ks<8;ks++){
      int kk = ks*16 + 2*tig;
      uint32_t a[2][4], b[4][2];
      #pragma unroll
      for (int mf=0;mf<2;mf++){
        int r = m0 + mf*16 + gid;
        a[mf][0] = LDU32(&Wc[r*136 + kk]);
        a[mf][1] = LDU32(&Wc[(r+8)*136 + kk]);
        a[mf][2] = LDU32(&Wc[r*136 + kk + 8]);
        a[mf][3] = LDU32(&Wc[(r+8)*136 + kk + 8]);
      }
      #pragma unroll
      for (int nf=0;nf<4;nf++){
        int col = n0 + nf*8 + gid;
        b[nf][0] = LDU32(&Yt[col*136 + kk]);
        b[nf][1] = LDU32(&Yt[col*136 + kk + 8]);
      }
      #pragma unroll
      for (int mf=0;mf<2;mf++)
        #pragma unroll
        for (int nf=0;nf<4;nf++) mmah(zacc[mf][nf], a[mf], b[nf]);
    }
  }

  __half* zp = g_z1 + (size_t)npv*SLAB;
  #pragma unroll
  for (int mf=0;mf<2;mf++){
    int r = m0 + mf*16 + gid;
    float bo0 = b_out[r], bo1 = b_out[r+8];
    float s0a=0.f, s0b=0.f, s1a=0.f, s1b=0.f;
    #pragma unroll
    for (int nf=0;nf<4;nf++){
      int col = n0 + nf*8 + 2*tig;
      float z00 = zacc[mf][nf][0]+bo0, z01 = zacc[mf][nf][1]+bo0;
      float z10 = zacc[mf][nf][2]+bo1, z11 = zacc[mf][nf][3]+bo1;
      *(__half2*)&zp[r*64 + col]     = __floats2half2_rn(z00, z01);
      *(__half2*)&zp[(r+8)*64 + col] = __floats2half2_rn(z10, z11);
      s0a += z00+z01; s0b += z00*z00+z01*z01;
      s1a += z10+z11; s1b += z10*z10+z11*z11;
    }
    #pragma unroll
    for (int off=1; off<4; off<<=1){
      s0a += __shfl_xor_sync(0xffffffffu, s0a, off);
      s0b += __shfl_xor_sync(0xffffffffu, s0b, off);
      s1a += __shfl_xor_sync(0xffffffffu, s1a, off);
      s1b += __shfl_xor_sync(0xffffffffu, s1b, off);
    }
    if (tig==0){
      atomicAdd(&g_sum[sbuf+r], s0a);   atomicAdd(&g_sq[sbuf+r], s0b);
      atomicAdd(&g_sum[sbuf+r+8], s1a); atomicAdd(&g_sq[sbuf+r+8], s1b);
    }
  }
}

// ---------------------------------------------------------------------------
// Fused BN1+residual+lrelu + FF conv (fp16 mma): y1 computed on the fly; z -> g_z2
__global__ void __launch_bounds__(256,2) k_ffb(const float* __restrict__ xres,
                                               const float* __restrict__ w_ff,
                                               const float* __restrict__ b_ff,
                                               const float* __restrict__ gamma1,
                                               const float* __restrict__ beta1,
                                               int sb1, int sb2){
  extern __shared__ __half smh[];
  __half* Xt = smh;           // [t=64][c=128] stride 136 (holds y1 fp16)
  __half* Wc = smh + 8704;    // [o=128][c=128] stride 136
  __shared__ float sc1[128], sh1[128];
  int npv = blockIdx.x;
  int tid = threadIdx.x, lane = tid&31, w = tid>>5;
  int m0 = (w&3)*32, n0 = (w>>2)*32;
  int gid = lane>>2, tig = lane&3;

  if (tid < 128){
    float mu  = g_sum[sb1+tid] * (1.0f/CNTf);
    float var = g_sq[sb1+tid]  * (1.0f/CNTf) - mu*mu;
    float sc  = gamma1[tid] * rsqrtf(var + EPSf);
    sc1[tid] = sc; sh1[tid] = beta1[tid] - mu*sc;
  }
  __syncthreads();

  const float4* xr4 = (const float4*)(xres + (size_t)npv*SLAB);
  const uint2*  z4  = (const uint2*)(g_z1 + (size_t)npv*SLAB);
  for (int i=tid;i<2048;i+=256){
    int c = i>>4, t0 = (i&15)<<2;
    float4 xv = xr4[i];
    uint2 zu = z4[i];
    __half2 za = *(__half2*)&zu.x, zb = *(__half2*)&zu.y;
    float s = sc1[c], h = sh1[c];
    Xt[(t0  )*136+c] = __float2half_rn(lrelu(xv.x + __low2float(za)*s + h));
    Xt[(t0+1)*136+c] = __float2half_rn(lrelu(xv.y + __high2float(za)*s + h));
    Xt[(t0+2)*136+c] = __float2half_rn(lrelu(xv.z + __low2float(zb)*s + h));
    Xt[(t0+3)*136+c] = __float2half_rn(lrelu(xv.w + __high2float(zb)*s + h));
  }
  for (int i=tid;i<128*32;i+=256){
    int o = i>>5, c0 = (i&31)<<2;
    *(uint2*)&Wc[o*136 + c0] = pack4(*(const float4*)&w_ff[o*128 + c0]);
  }
  __syncthreads();

  float acc[2][4][4];
  #pragma unroll
  for (int mf=0;mf<2;mf++)
    #pragma unroll
    for (int nf=0;nf<4;nf++){ acc[mf][nf][0]=acc[mf][nf][1]=acc[mf][nf][2]=acc[mf][nf][3]=0.f; }

  #pragma unroll
  for (int ks=0;ks<8;ks++){
    int kk = ks*16 + 2*tig;
    uint32_t a[2][4], b[4][2];
    #pragma unroll
    for (int mf=0;mf<2;mf++){
      int r = m0 + mf*16 + gid;
      a[mf][0] = LDU32(&Wc[r*136 + kk]);
      a[mf][1] = LDU32(&Wc[(r+8)*136 + kk]);
      a[mf][2] = LDU32(&Wc[r*136 + kk + 8]);
      a[mf][3] = LDU32(&Wc[(r+8)*136 + kk + 8]);
    }
    #pragma unroll
    for (int nf=0;nf<4;nf++){
      int col = n0 + nf*8 + gid;
      b[nf][0] = LDU32(&Xt[col*136 + kk]);
      b[nf][1] = LDU32(&Xt[col*136 + kk + 8]);
    }
    #pragma unroll
    for (int mf=0;mf<2;mf++)
      #pragma unroll
      for (int nf=0;nf<4;nf++) mmah(acc[mf][nf], a[mf], b[nf]);
  }
  __half* zp = g_z2 + (size_t)npv*SLAB;
  #pragma unroll
  for (int mf=0;mf<2;mf++){
    int r = m0 + mf*16 + gid;
    float bo0 = b_ff[r], bo1 = b_ff[r+8];
    float s0a=0.f, s0b=0.f, s1a=0.f, s1b=0.f;
    #pragma unroll
    for (int nf=0;nf<4;nf++){
      int col = n0 + nf*8 + 2*tig;
      float z00 = acc[mf][nf][0]+bo0, z01 = acc[mf][nf][1]+bo0;
      float z10 = acc[mf][nf][2]+bo1, z11 = acc[mf][nf][3]+bo1;
      *(__half2*)&zp[r*64 + col]     = __floats2half2_rn(z00, z01);
      *(__half2*)&zp[(r+8)*64 + col] = __floats2half2_rn(z10, z11);
      s0a += z00+z01; s0b += z00*z00+z01*z01;
      s1a += z10+z11; s1b += z10*z10+z11*z11;
    }
    #pragma unroll
    for (int off=1; off<4; off<<=1){
      s0a += __shfl_xor_sync(0xffffffffu, s0a, off);
      s0b += __shfl_xor_sync(0xffffffffu, s0b, off);
      s1a += __shfl_xor_sync(0xffffffffu, s1a, off);
      s1b += __shfl_xor_sync(0xffffffffu, s1b, off);
    }
    if (tig==0){
      atomicAdd(&g_sum[sb2+r], s0a);   atomicAdd(&g_sq[sb2+r], s0b);
      atomicAdd(&g_sum[sb2+r+8], s1a); atomicAdd(&g_sq[sb2+r+8], s1b);
    }
  }
}

// ---------------------------------------------------------------------------
// Recompute y1, apply BN2 + residual + lrelu; write fp32 + fp16 outputs
__global__ void k_bnres2(const float* __restrict__ xres,
                         float* __restrict__ out, __half* __restrict__ out16,
                         const float* __restrict__ g1, const float* __restrict__ b1,
                         const float* __restrict__ g2, const float* __restrict__ b2,
                         int sb1, int sb2){
  size_t i4 = (size_t)blockIdx.x*256 + threadIdx.x;
  int c = (int)((i4 >> 4) & 127);
  float mu1  = g_sum[sb1+c] * (1.0f/CNTf);
  float var1 = g_sq[sb1+c]  * (1.0f/CNTf) - mu1*mu1;
  float s1 = g1[c] * rsqrtf(var1 + EPSf);
  float h1 = b1[c] - mu1*s1;
  float mu2  = g_sum[sb2+c] * (1.0f/CNTf);
  float var2 = g_sq[sb2+c]  * (1.0f/CNTf) - mu2*mu2;
  float s2 = g2[c] * rsqrtf(var2 + EPSf);
  float h2 = b2[c] - mu2*s2;
  float4 xr = ((const float4*)xres)[i4];
  uint2 u1 = ((const uint2*)g_z1)[i4];
  uint2 u2 = ((const uint2*)g_z2)[i4];
  __half2 z1a = *(__half2*)&u1.x, z1b = *(__half2*)&u1.y;
  __half2 z2a = *(__half2*)&u2.x, z2b = *(__half2*)&u2.y;
  float y0 = lrelu(xr.x + __low2float(z1a)*s1 + h1);
  float y1 = lrelu(xr.y + __high2float(z1a)*s1 + h1);
  float y2 = lrelu(xr.z + __low2float(z1b)*s1 + h1);
  float y3 = lrelu(xr.w + __high2float(z1b)*s1 + h1);
  float4 o;
  o.x = lrelu(y0 + __low2float(z2a)*s2 + h2);
  o.y = lrelu(y1 + __high2float(z2a)*s2 + h2);
  o.z = lrelu(y2 + __low2float(z2b)*s2 + h2);
  o.w = lrelu(y3 + __high2float(z2b)*s2 + h2);
  ((float4*)out)[i4] = o;
  uint2 oh; 
  __half2 ha = __floats2half2_rn(o.x, o.y), hb = __floats2half2_rn(o.z, o.w);
  oh.x = *(uint32_t*)&ha; oh.y = *(uint32_t*)&hb;
  ((uint2*)out16)[i4] = oh;
}

__global__ void k_zero(){
  int i = blockIdx.x*256 + threadIdx.x;
  if (i < 512){ g_sum[i] = 0.f; g_sq[i] = 0.f; }
}

// ---------------------------------------------------------------------------
extern "C" void kernel_launch(void* const* d_in, const int* in_sizes, int n_in,
                              void* d_out, int out_size){
  const float* x     = (const float*)d_in[0];
  const float* att1  = (const float*)d_in[1];
  const float* att2  = (const float*)d_in[2];
  const float* alpt  = (const float*)d_in[3];
  const float* w_in  = (const float*)d_in[4];
  const float* b_in  = (const float*)d_in[5];
  const float* w_out = (const float*)d_in[6];
  const float* b_out = (const float*)d_in[7];
  const float* g_o   = (const float*)d_in[8];
  const float* be_o  = (const float*)d_in[9];
  const float* w_ff  = (const float*)d_in[10];
  const float* b_ff  = (const float*)d_in[11];
  const float* g_f   = (const float*)d_in[12];
  const float* be_f  = (const float*)d_in[13];

  float *px0, *px1;
  __half *px0h, *px1h;
  cudaGetSymbolAddress((void**)&px0,  g_x0);
  cudaGetSymbolAddress((void**)&px1,  g_x1);
  cudaGetSymbolAddress((void**)&px0h, g_x0h);
  cudaGetSymbolAddress((void**)&px1h, g_x1h);

  const int SM_QK = (8704 + 192*136)*2;   // 69632 B
  const int SM_AV = (22528 + 128*136)*2;  // 79872 B
  const int SM_FF = (8704 + 128*136)*2;   // 52224 B
  cudaFuncSetAttribute(k_qk,  cudaFuncAttributeMaxDynamicSharedMemorySize, SM_QK);
  cudaFuncSetAttribute(k_av,  cudaFuncAttributeMaxDynamicSharedMemorySize, SM_AV);
  cudaFuncSetAttribute(k_ffb, cudaFuncAttributeMaxDynamicSharedMemorySize, SM_FF);

  k_zero<<<2,256>>>();
  k_tin<<<dim3(256,192), dim3(32,8)>>>(x);

  auto run_block = [&](const float* attb, const float* xres, const __half* x16,
                       float* outb, __half* outh, int sb){
    k_qk <<<NPVd,256,SM_QK>>>(x16, w_in, b_in);
    k_att<<<NN*Sd*PPd,256>>>(attb, alpt);
    k_av <<<NPVd,256,SM_AV>>>(x16, w_out, b_out, sb*128);
    k_ffb<<<NPVd,256,SM_FF>>>(xres, w_ff, b_ff, g_o, be_o, sb*128, (sb+1)*128);
    k_bnres2<<<TOTd/4/256,256>>>(xres, outb, outh, g_o, be_o, g_f, be_f, sb*128, (sb+1)*128);
  };

  run_block(att1, px0, px0h, px1, px1h, 0);
  run_block(att2, px1, px1h, px0, px0h, 2);

  k_tout<<<dim3(256,192), dim3(32,8)>>>(px0, (float*)d_out);
}

// round 14
// speedup vs baseline: 1.9616x; 1.1831x over previous
#include <cuda_runtime.h>
#include <cuda_fp16.h>
#include <math.h>
#include <stdint.h>

#define NN  32
#define PPd 6
#define Cd  128
#define Td  64
#define Vd  25
#define Sd  3
#define CId 32
#define NPd   (NN*PPd)
#define NPVd  (NPd*Vd)        // 4800
#define SLAB  (Cd*Td)         // 8192
#define QKOd  (2*Sd*CId)      // 192
#define TOTd  (NPVd*SLAB)
#define CNTf  307200.0f
#define EPSf  1e-5f
#define NEGf  0.1f

__device__ float  g_x0[TOTd];
__device__ float  g_x1[TOTd];
__device__ __half g_x0h[TOTd];
__device__ __half g_x1h[TOTd];
__device__ __half g_z1[TOTd];
__device__ __half g_z2[TOTd];
__device__ __half g_qk16[NPVd*QKOd*Td];     // [npv][t=64][o=192] fp16
__device__ __half g_att16[NN*Sd*PPd*Td*Td]; // [b][q=64][t=64] fp16
__device__ float  g_sum[512];
__device__ float  g_sq [512];
__device__ __half g_w16in [192*128];
__device__ __half g_w16out[128*384];
__device__ __half g_w16ff [128*128];

__device__ __forceinline__ float lrelu(float x){ return x >= 0.f ? x : NEGf*x; }

// m16n8k16 fp16 MMA, fp32 accumulate
__device__ __forceinline__ void mmah(float c[4], const uint32_t a[4], const uint32_t b[2]){
  asm volatile(
    "mma.sync.aligned.m16n8k16.row.col.f32.f16.f16.f32 "
    "{%0,%1,%2,%3},{%4,%5,%6,%7},{%8,%9},{%0,%1,%2,%3};\n"
    : "+f"(c[0]),"+f"(c[1]),"+f"(c[2]),"+f"(c[3])
    : "r"(a[0]),"r"(a[1]),"r"(a[2]),"r"(a[3]),"r"(b[0]),"r"(b[1]));
}
#define LDU32(p) (*(const uint32_t*)(p))

// ---------------------------------------------------------------------------
// Weight fp32 -> fp16 images (natural layouts), once per launch
__global__ void k_prep16(const float* __restrict__ w_in,
                         const float* __restrict__ w_out,
                         const float* __restrict__ w_ff){
  int i = blockIdx.x*256 + threadIdx.x;
  if (i < 192*128){ g_w16in[i] = __float2half_rn(w_in[i]); }
  else if (i < 192*128 + 128*384){ int j = i - 192*128; g_w16out[j] = __float2half_rn(w_out[j]); }
  else if (i < 192*128 + 128*384 + 128*128){ int k = i - 192*128 - 128*384; g_w16ff[k] = __float2half_rn(w_ff[k]); }
}

// ---------------------------------------------------------------------------
// Input transpose: x[(n,p)][c][t][v] -> g_x0[(n,p)][v][c][t] (fp32 + fp16)
__global__ void k_tin(const float* __restrict__ x){
  __shared__ float tile[32][33];
  int np = blockIdx.y, m0 = blockIdx.x*32;
  const float* src = x + (size_t)np*(Cd*Td*Vd);
  float*  dst  = g_x0  + (size_t)np*(Vd*SLAB);
  __half* dsth = g_x0h + (size_t)np*(Vd*SLAB);
  int tx = threadIdx.x, ty = threadIdx.y;
  #pragma unroll
  for (int k=0;k<4;k++){ int m = m0 + ty + k*8; if (tx < Vd) tile[ty+k*8][tx] = src[(size_t)m*Vd + tx]; }
  __syncthreads();
  #pragma unroll
  for (int k=0;k<4;k++){
    int v = ty + k*8;
    if (v < Vd){
      float val = tile[tx][v];
      dst [(size_t)v*SLAB + m0 + tx] = val;
      dsth[(size_t)v*SLAB + m0 + tx] = __float2half_rn(val);
    }
  }
}
__global__ void k_tout(const float* __restrict__ srcb, float* __restrict__ dst){
  __shared__ float tile[32][33];
  int np = blockIdx.y, m0 = blockIdx.x*32;
  const float* src = srcb + (size_t)np*(Vd*SLAB);
  float* d = dst + (size_t)np*(Cd*Td*Vd);
  int tx = threadIdx.x, ty = threadIdx.y;
  #pragma unroll
  for (int k=0;k<4;k++){ int v = ty + k*8; if (v < Vd) tile[v][tx] = src[(size_t)v*SLAB + m0 + tx]; }
  __syncthreads();
  #pragma unroll
  for (int k=0;k<4;k++){ int m = m0 + ty + k*8; if (tx < Vd) d[(size_t)m*Vd + tx] = tile[tx][ty + k*8]; }
}

// ---------------------------------------------------------------------------
// QK conv (fp16 mma, swapped operands): OutT[t=64][o=192] = X^T * W^T + b
// A = Xt[t][c] (m=t,k=c), B = Wc[o][c] (n=o,k=c). Warps: 2 in M x 4 in N.
__global__ void __launch_bounds__(256,2) k_qk(const __half* __restrict__ in16,
                                              const float* __restrict__ b_in){
  extern __shared__ __half smh[];
  __half* Xt = smh;           // [t=64][c=128] stride 136
  __half* Wc = smh + 8704;    // [o=192][c=128] stride 136
  int npv = blockIdx.x;
  int tid = threadIdx.x, lane = tid&31, w = tid>>5;
  int m0 = (w&1)*32, n0 = (w>>1)*48;
  int gid = lane>>2, tig = lane&3;

  const uint4* xin = (const uint4*)(in16 + (size_t)npv*SLAB);
  for (int i=tid;i<1024;i+=256){
    int c = i>>3, t0 = (i&7)<<3;
    uint4 u = xin[i];
    __half2 h01=*(__half2*)&u.x, h23=*(__half2*)&u.y, h45=*(__half2*)&u.z, h67=*(__half2*)&u.w;
    Xt[(t0+0)*136+c]=__low2half(h01); Xt[(t0+1)*136+c]=__high2half(h01);
    Xt[(t0+2)*136+c]=__low2half(h23); Xt[(t0+3)*136+c]=__high2half(h23);
    Xt[(t0+4)*136+c]=__low2half(h45); Xt[(t0+5)*136+c]=__high2half(h45);
    Xt[(t0+6)*136+c]=__low2half(h67); Xt[(t0+7)*136+c]=__high2half(h67);
  }
  for (int i=tid;i<3072;i+=256){
    int o = i>>4, c0 = (i&15)<<3;
    *(uint4*)&Wc[o*136 + c0] = *(const uint4*)&g_w16in[o*128 + c0];
  }
  __syncthreads();

  float acc[2][6][4];
  #pragma unroll
  for (int mf=0;mf<2;mf++)
    #pragma unroll
    for (int nf=0;nf<6;nf++){ acc[mf][nf][0]=acc[mf][nf][1]=acc[mf][nf][2]=acc[mf][nf][3]=0.f; }

  #pragma unroll
  for (int ks=0;ks<8;ks++){
    int kk = ks*16 + 2*tig;
    uint32_t a[2][4], b[6][2];
    #pragma unroll
    for (int mf=0;mf<2;mf++){
      int r = m0 + mf*16 + gid;
      a[mf][0] = LDU32(&Xt[r*136 + kk]);
      a[mf][1] = LDU32(&Xt[(r+8)*136 + kk]);
      a[mf][2] = LDU32(&Xt[r*136 + kk + 8]);
      a[mf][3] = LDU32(&Xt[(r+8)*136 + kk + 8]);
    }
    #pragma unroll
    for (int nf=0;nf<6;nf++){
      int col = n0 + nf*8 + gid;
      b[nf][0] = LDU32(&Wc[col*136 + kk]);
      b[nf][1] = LDU32(&Wc[col*136 + kk + 8]);
    }
    #pragma unroll
    for (int mf=0;mf<2;mf++)
      #pragma unroll
      for (int nf=0;nf<6;nf++) mmah(acc[mf][nf], a[mf], b[nf]);
  }
  __half* outp = g_qk16 + (size_t)npv*QKOd*Td;   // [t][192]
  #pragma unroll
  for (int mf=0;mf<2;mf++){
    int r = m0 + mf*16 + gid;
    #pragma unroll
    for (int nf=0;nf<6;nf++){
      int col = n0 + nf*8 + 2*tig;
      float bb0 = b_in[col], bb1 = b_in[col+1];
      *(__half2*)&outp[r*192 + col]     = __floats2half2_rn(acc[mf][nf][0]+bb0, acc[mf][nf][1]+bb1);
      *(__half2*)&outp[(r+8)*192 + col] = __floats2half2_rn(acc[mf][nf][2]+bb0, acc[mf][nf][3]+bb1);
    }
  }
}

// ---------------------------------------------------------------------------
// Attention scores (fp16 mma): per (n,s,p): scores[t][q] over K=(c=32)x(v=25)
// staging from g_qk16 [t][192] is pure uint4 copies; 2 v per iteration.
__global__ void __launch_bounds__(256) k_att(const float* __restrict__ attb,
                                             const float* __restrict__ alphat){
  __shared__ __align__(16) __half Qs[64*72];   // [t][ck=64] stride 72
  __shared__ __align__(16) __half Ks[64*72];   // [q][ck=64] stride 72
  int b = blockIdx.x;
  int p = b % PPd; int s = (b/PPd) % Sd; int n = b/(PPd*Sd);
  int np = n*PPd + p;
  int tid = threadIdx.x, lane = tid&31, w = tid>>5;
  int m0 = (w&3)*16, n0 = (w>>2)*32;
  int gid = lane>>2, tig = lane&3;

  float acc[4][4];
  #pragma unroll
  for (int nf=0;nf<4;nf++){ acc[nf][0]=acc[nf][1]=acc[nf][2]=acc[nf][3]=0.f; }

  const __half* base_np = g_qk16 + (size_t)np*Vd*(QKOd*Td);
  for (int vp=0; vp<13; vp++){
    __syncthreads();
    for (int i=tid;i<1024;i+=256){
      int m = i>>9, r = (i>>3)&63, j = i&7;
      int v = vp*2 + (j>>2);
      uint4 u = make_uint4(0,0,0,0);
      if (v < Vd)
        u = *(const uint4*)(base_np + (size_t)v*(QKOd*Td) + r*192 + (m?96:0) + s*32 + (j&3)*8);
      *(uint4*)&((m?Ks:Qs)[r*72 + j*8]) = u;
    }
    __syncthreads();
    #pragma unroll
    for (int ks=0;ks<4;ks++){
      int kk = ks*16 + 2*tig;
      uint32_t a[4], bb[4][2];
      int r = m0 + gid;
      a[0] = LDU32(&Qs[r*72 + kk]);
      a[1] = LDU32(&Qs[(r+8)*72 + kk]);
      a[2] = LDU32(&Qs[r*72 + kk + 8]);
      a[3] = LDU32(&Qs[(r+8)*72 + kk + 8]);
      #pragma unroll
      for (int nf=0;nf<4;nf++){
        int col = n0 + nf*8 + gid;
        bb[nf][0] = LDU32(&Ks[col*72 + kk]);
        bb[nf][1] = LDU32(&Ks[col*72 + kk + 8]);
      }
      #pragma unroll
      for (int nf=0;nf<4;nf++) mmah(acc[nf], a, bb[nf]);
    }
  }
  float al = alphat[s];
  const float* bp = attb + (size_t)s*Td*Td;
  __syncthreads();
  // write att transposed [q][t] fp16 into Qs, then vector-copy out
  #pragma unroll
  for (int nf=0;nf<4;nf++){
    int t = m0 + gid, q = n0 + nf*8 + 2*tig;
    float v00 = bp[t*Td+q]       + tanhf(acc[nf][0]*(1.f/800.f))*al;
    float v01 = bp[t*Td+q+1]     + tanhf(acc[nf][1]*(1.f/800.f))*al;
    float v10 = bp[(t+8)*Td+q]   + tanhf(acc[nf][2]*(1.f/800.f))*al;
    float v11 = bp[(t+8)*Td+q+1] + tanhf(acc[nf][3]*(1.f/800.f))*al;
    Qs[q*72 + t]       = __float2half_rn(v00);
    Qs[(q+1)*72 + t]   = __float2half_rn(v01);
    Qs[q*72 + t + 8]   = __float2half_rn(v10);
    Qs[(q+1)*72 + t+8] = __float2half_rn(v11);
  }
  __syncthreads();
  __half* attp = g_att16 + (size_t)b*Td*Td;   // [q][t]
  for (int i=tid;i<512;i+=256){
    int q = i>>3, j = i&7;
    *(uint4*)&attp[q*64 + j*8] = *(const uint4*)&Qs[q*72 + j*8];
  }
}

// ---------------------------------------------------------------------------
// Fused att-apply + S*C->C conv + BN stats (fp16 mma). z -> g_z1
__global__ void __launch_bounds__(256,2) k_av(const __half* __restrict__ in16,
                                              const float* __restrict__ b_out,
                                              int sbuf){
  extern __shared__ __half smh[];
  __half* Xa   = smh;           // [c=128][t=64]  stride 72
  __half* attT = smh + 9216;    // [q=64][t=64]   stride 72
  __half* Yt   = smh + 13824;   // [q=64][c=128]  stride 136
  __half* Wc   = smh + 22528;   // [o=128][c=128] stride 136
  int npv = blockIdx.x;
  int np = npv / Vd;
  int p = np % PPd, n = np / PPd;
  int tid = threadIdx.x, lane = tid&31, w = tid>>5;
  int m0 = (w&3)*32, n0 = (w>>2)*32;
  int gid = lane>>2, tig = lane&3;

  const uint4* xin = (const uint4*)(in16 + (size_t)npv*SLAB);
  for (int i=tid;i<1024;i+=256){
    int c = i>>3, t0 = (i&7)<<3;
    *(uint4*)&Xa[c*72 + t0] = xin[i];
  }
  float zacc[2][4][4];
  #pragma unroll
  for (int mf=0;mf<2;mf++)
    #pragma unroll
    for (int nf=0;nf<4;nf++){ zacc[mf][nf][0]=zacc[mf][nf][1]=zacc[mf][nf][2]=zacc[mf][nf][3]=0.f; }

  for (int s=0;s<Sd;s++){
    __syncthreads();
    const __half* a16 = g_att16 + ((size_t)((n*Sd+s)*PPd+p))*Td*Td;
    for (int i=tid;i<512;i+=256){
      int q = i>>3, j = i&7;
      *(uint4*)&attT[q*72 + j*8] = *(const uint4*)&a16[q*64 + j*8];
    }
    for (int i=tid;i<2048;i+=256){
      int o = i>>4, c0 = (i&15)<<3;
      *(uint4*)&Wc[o*136 + c0] = *(const uint4*)&g_w16out[o*384 + s*128 + c0];
    }
    __syncthreads();

    // Stage 1: Y = Xa * attT  (m=c, n=q, k=t)
    float yacc[2][4][4];
    #pragma unroll
    for (int mf=0;mf<2;mf++)
      #pragma unroll
      for (int nf=0;nf<4;nf++){ yacc[mf][nf][0]=yacc[mf][nf][1]=yacc[mf][nf][2]=yacc[mf][nf][3]=0.f; }
    #pragma unroll
    for (int ks=0;ks<4;ks++){
      int kk = ks*16 + 2*tig;
      uint32_t a[2][4], b[4][2];
      #pragma unroll
      for (int mf=0;mf<2;mf++){
        int r = m0 + mf*16 + gid;
        a[mf][0] = LDU32(&Xa[r*72 + kk]);
        a[mf][1] = LDU32(&Xa[(r+8)*72 + kk]);
        a[mf][2] = LDU32(&Xa[r*72 + kk + 8]);
        a[mf][3] = LDU32(&Xa[(r+8)*72 + kk + 8]);
      }
      #pragma unroll
      for (int nf=0;nf<4;nf++){
        int col = n0 + nf*8 + gid;
        b[nf][0] = LDU32(&attT[col*72 + kk]);
        b[nf][1] = LDU32(&attT[col*72 + kk + 8]);
      }
      #pragma unroll
      for (int mf=0;mf<2;mf++)
        #pragma unroll
        for (int nf=0;nf<4;nf++) mmah(yacc[mf][nf], a[mf], b[nf]);
    }
    #pragma unroll
    for (int mf=0;mf<2;mf++){
      int c = m0 + mf*16 + gid;
      #pragma unroll
      for (int nf=0;nf<4;nf++){
        int q = n0 + nf*8 + 2*tig;
        Yt[q*136 + c]       = __float2half_rn(yacc[mf][nf][0]);
        Yt[(q+1)*136 + c]   = __float2half_rn(yacc[mf][nf][1]);
        Yt[q*136 + c + 8]   = __float2half_rn(yacc[mf][nf][2]);
        Yt[(q+1)*136 + c+8] = __float2half_rn(yacc[mf][nf][3]);
      }
    }
    __syncthreads();

    // Stage 2: Z += Wc * Yt  (m=o, n=q, k=c)
    #pragma unroll
    for (int ks=0;ks<8;ks++){
      int kk = ks*16 + 2*tig;
      uint32_t a[2][4], b[4][2];
      #pragma unroll
      for (int mf=0;mf<2;mf++){
        int r = m0 + mf*16 + gid;
        a[mf][0] = LDU32(&Wc[r*136 + kk]);
        a[mf][1] = LDU32(&Wc[(r+8)*136 + kk]);
        a[mf][2] = LDU32(&Wc[r*136 + kk + 8]);
        a[mf][3] = LDU32(&Wc[(r+8)*136 + kk + 8]);
      }
      #pragma unroll
      for (int nf=0;nf<4;nf++){
        int col = n0 + nf*8 + gid;
        b[nf][0] = LDU32(&Yt[col*136 + kk]);
        b[nf][1] = LDU32(&Yt[col*136 + kk + 8]);
      }
      #pragma unroll
      for (int mf=0;mf<2;mf++)
        #pragma unroll
        for (int nf=0;nf<4;nf++) mmah(zacc[mf][nf], a[mf], b[nf]);
    }
  }

  __half* zp = g_z1 + (size_t)npv*SLAB;
  #pragma unroll
  for (int mf=0;mf<2;mf++){
    int r = m0 + mf*16 + gid;
    float bo0 = b_out[r], bo1 = b_out[r+8];
    float s0a=0.f, s0b=0.f, s1a=0.f, s1b=0.f;
    #pragma unroll
    for (int nf=0;nf<4;nf++){
      int col = n0 + nf*8 + 2*tig;
      float z00 = zacc[mf][nf][0]+bo0, z01 = zacc[mf][nf][1]+bo0;
      float z10 = zacc[mf][nf][2]+bo1, z11 = zacc[mf][nf][3]+bo1;
      *(__half2*)&zp[r*64 + col]     = __floats2half2_rn(z00, z01);
      *(__half2*)&zp[(r+8)*64 + col] = __floats2half2_rn(z10, z11);
      s0a += z00+z01; s0b += z00*z00+z01*z01;
      s1a += z10+z11; s1b += z10*z10+z11*z11;
    }
    #pragma unroll
    for (int off=1; off<4; off<<=1){
      s0a += __shfl_xor_sync(0xffffffffu, s0a, off);
      s0b += __shfl_xor_sync(0xffffffffu, s0b, off);
      s1a += __shfl_xor_sync(0xffffffffu, s1a, off);
      s1b += __shfl_xor_sync(0xffffffffu, s1b, off);
    }
    if (tig==0){
      atomicAdd(&g_sum[sbuf+r], s0a);   atomicAdd(&g_sq[sbuf+r], s0b);
      atomicAdd(&g_sum[sbuf+r+8], s1a); atomicAdd(&g_sq[sbuf+r+8], s1b);
    }
  }
}

// ---------------------------------------------------------------------------
// Fused BN1+residual+lrelu + FF conv (fp16 mma): y1 on the fly; z -> g_z2
__global__ void __launch_bounds__(256,2) k_ffb(const float* __restrict__ xres,
                                               const float* __restrict__ b_ff,
                                               const float* __restrict__ gamma1,
                                               const float* __restrict__ beta1,
                                               int sb1, int sb2){
  extern __shared__ __half smh[];
  __half* Xt = smh;           // [t=64][c=128] stride 136 (y1 fp16)
  __half* Wc = smh + 8704;    // [o=128][c=128] stride 136
  __shared__ float sc1[128], sh1[128];
  int npv = blockIdx.x;
  int tid = threadIdx.x, lane = tid&31, w = tid>>5;
  int m0 = (w&3)*32, n0 = (w>>2)*32;
  int gid = lane>>2, tig = lane&3;

  if (tid < 128){
    float mu  = g_sum[sb1+tid] * (1.0f/CNTf);
    float var = g_sq[sb1+tid]  * (1.0f/CNTf) - mu*mu;
    float sc  = gamma1[tid] * rsqrtf(var + EPSf);
    sc1[tid] = sc; sh1[tid] = beta1[tid] - mu*sc;
  }
  __syncthreads();

  const float4* xr4 = (const float4*)(xres + (size_t)npv*SLAB);
  const uint2*  z4  = (const uint2*)(g_z1 + (size_t)npv*SLAB);
  for (int i=tid;i<2048;i+=256){
    int c = i>>4, t0 = (i&15)<<2;
    float4 xv = xr4[i];
    uint2 zu = z4[i];
    __half2 za = *(__half2*)&zu.x, zb = *(__half2*)&zu.y;
    float s = sc1[c], h = sh1[c];
    Xt[(t0  )*136+c] = __float2half_rn(lrelu(xv.x + __low2float(za)*s + h));
    Xt[(t0+1)*136+c] = __float2half_rn(lrelu(xv.y + __high2float(za)*s + h));
    Xt[(t0+2)*136+c] = __float2half_rn(lrelu(xv.z + __low2float(zb)*s + h));
    Xt[(t0+3)*136+c] = __float2half_rn(lrelu(xv.w + __high2float(zb)*s + h));
  }
  for (int i=tid;i<2048;i+=256){
    int o = i>>4, c0 = (i&15)<<3;
    *(uint4*)&Wc[o*136 + c0] = *(const uint4*)&g_w16ff[o*128 + c0];
  }
  __syncthreads();

  float acc[2][4][4];
  #pragma unroll
  for (int mf=0;mf<2;mf++)
    #pragma unroll
    for (int nf=0;nf<4;nf++){ acc[mf][nf][0]=acc[mf][nf][1]=acc[mf][nf][2]=acc[mf][nf][3]=0.f; }

  #pragma unroll
  for (int ks=0;ks<8;ks++){
    int kk = ks*16 + 2*tig;
    uint32_t a[2][4], b[4][2];
    #pragma unroll
    for (int mf=0;mf<2;mf++){
      int r = m0 + mf*16 + gid;
      a[mf][0] = LDU32(&Wc[r*136 + kk]);
      a[mf][1] = LDU32(&Wc[(r+8)*136 + kk]);
      a[mf][2] = LDU32(&Wc[r*136 + kk + 8]);
      a[mf][3] = LDU32(&Wc[(r+8)*136 + kk + 8]);
    }
    #pragma unroll
    for (int nf=0;nf<4;nf++){
      int col = n0 + nf*8 + gid;
      b[nf][0] = LDU32(&Xt[col*136 + kk]);
      b[nf][1] = LDU32(&Xt[col*136 + kk + 8]);
    }
    #pragma unroll
    for (int mf=0;mf<2;mf++)
      #pragma unroll
      for (int nf=0;nf<4;nf++) mmah(acc[mf][nf], a[mf], b[nf]);
  }
  __half* zp = g_z2 + (size_t)npv*SLAB;
  #pragma unroll
  for (int mf=0;mf<2;mf++){
    int r = m0 + mf*16 + gid;
    float bo0 = b_ff[r], bo1 = b_ff[r+8];
    float s0a=0.f, s0b=0.f, s1a=0.f, s1b=0.f;
    #pragma unroll
    for (int nf=0;nf<4;nf++){
      int col = n0 + nf*8 + 2*tig;
      float z00 = acc[mf][nf][0]+bo0, z01 = acc[mf][nf][1]+bo0;
      float z10 = acc[mf][nf][2]+bo1, z11 = acc[mf][nf][3]+bo1;
      *(__half2*)&zp[r*64 + col]     = __floats2half2_rn(z00, z01);
      *(__half2*)&zp[(r+8)*64 + col] = __floats2half2_rn(z10, z11);
      s0a += z00+z01; s0b += z00*z00+z01*z01;
      s1a += z10+z11; s1b += z10*z10+z11*z11;
    }
    #pragma unroll
    for (int off=1; off<4; off<<=1){
      s0a += __shfl_xor_sync(0xffffffffu, s0a, off);
      s0b += __shfl_xor_sync(0xffffffffu, s0b, off);
      s1a += __shfl_xor_sync(0xffffffffu, s1a, off);
      s1b += __shfl_xor_sync(0xffffffffu, s1b, off);
    }
    if (tig==0){
      atomicAdd(&g_sum[sb2+r], s0a);   atomicAdd(&g_sq[sb2+r], s0b);
      atomicAdd(&g_sum[sb2+r+8], s1a); atomicAdd(&g_sq[sb2+r+8], s1b);
    }
  }
}

// ---------------------------------------------------------------------------
// Recompute y1, apply BN2 + residual + lrelu; write fp32 + fp16 outputs
__global__ void k_bnres2(const float* __restrict__ xres,
                         float* __restrict__ out, __half* __restrict__ out16,
                         const float* __restrict__ g1, const float* __restrict__ b1,
                         const float* __restrict__ g2, const float* __restrict__ b2,
                         int sb1, int sb2){
  size_t i4 = (size_t)blockIdx.x*256 + threadIdx.x;
  int c = (int)((i4 >> 4) & 127);
  float mu1  = g_sum[sb1+c] * (1.0f/CNTf);
  float var1 = g_sq[sb1+c]  * (1.0f/CNTf) - mu1*mu1;
  float s1 = g1[c] * rsqrtf(var1 + EPSf);
  float h1 = b1[c] - mu1*s1;
  float mu2  = g_sum[sb2+c] * (1.0f/CNTf);
  float var2 = g_sq[sb2+c]  * (1.0f/CNTf) - mu2*mu2;
  float s2 = g2[c] * rsqrtf(var2 + EPSf);
  float h2 = b2[c] - mu2*s2;
  float4 xr = ((const float4*)xres)[i4];
  uint2 u1 = ((const uint2*)g_z1)[i4];
  uint2 u2 = ((const uint2*)g_z2)[i4];
  __half2 z1a = *(__half2*)&u1.x, z1b = *(__half2*)&u1.y;
  __half2 z2a = *(__half2*)&u2.x, z2b = *(__half2*)&u2.y;
  float y0 = lrelu(xr.x + __low2float(z1a)*s1 + h1);
  float y1 = lrelu(xr.y + __high2float(z1a)*s1 + h1);
  float y2 = lrelu(xr.z + __low2float(z1b)*s1 + h1);
  float y3 = lrelu(xr.w + __high2float(z1b)*s1 + h1);
  float4 o;
  o.x = lrelu(y0 + __low2float(z2a)*s2 + h2);
  o.y = lrelu(y1 + __high2float(z2a)*s2 + h2);
  o.z = lrelu(y2 + __low2float(z2b)*s2 + h2);
  o.w = lrelu(y3 + __high2float(z2b)*s2 + h2);
  ((float4*)out)[i4] = o;
  uint2 oh;
  __half2 ha = __floats2half2_rn(o.x, o.y), hb = __floats2half2_rn(o.z, o.w);
  oh.x = *(uint32_t*)&ha; oh.y = *(uint32_t*)&hb;
  ((uint2*)out16)[i4] = oh;
}

__global__ void k_zero(){
  int i = blockIdx.x*256 + threadIdx.x;
  if (i < 512){ g_sum[i] = 0.f; g_sq[i] = 0.f; }
}

// ---------------------------------------------------------------------------
extern "C" void kernel_launch(void* const* d_in, const int* in_sizes, int n_in,
                              void* d_out, int out_size){
  const float* x     = (const float*)d_in[0];
  const float* att1  = (const float*)d_in[1];
  const float* att2  = (const float*)d_in[2];
  const float* alpt  = (const float*)d_in[3];
  const float* w_in  = (const float*)d_in[4];
  const float* b_in  = (const float*)d_in[5];
  const float* w_out = (const float*)d_in[6];
  const float* b_out = (const float*)d_in[7];
  const float* g_o   = (const float*)d_in[8];
  const float* be_o  = (const float*)d_in[9];
  const float* w_ff  = (const float*)d_in[10];
  const float* b_ff  = (const float*)d_in[11];
  const float* g_f   = (const float*)d_in[12];
  const float* be_f  = (const float*)d_in[13];

  float *px0, *px1;
  __half *px0h, *px1h;
  cudaGetSymbolAddress((void**)&px0,  g_x0);
  cudaGetSymbolAddress((void**)&px1,  g_x1);
  cudaGetSymbolAddress((void**)&px0h, g_x0h);
  cudaGetSymbolAddress((void**)&px1h, g_x1h);

  const int SM_QK = (8704 + 192*136)*2;   // 69632 B
  const int SM_AV = (22528 + 128*136)*2;  // 79872 B
  const int SM_FF = (8704 + 128*136)*2;   // 52224 B
  cudaFuncSetAttribute(k_qk,  cudaFuncAttributeMaxDynamicSharedMemorySize, SM_QK);
  cudaFuncSetAttribute(k_av,  cudaFuncAttributeMaxDynamicSharedMemorySize, SM_AV);
  cudaFuncSetAttribute(k_ffb, cudaFuncAttributeMaxDynamicSharedMemorySize, SM_FF);

  k_prep16<<<352,256>>>(w_in, w_out, w_ff);
  k_zero<<<2,256>>>();
  k_tin<<<dim3(256,192), dim3(32,8)>>>(x);

  auto run_block = [&](const float* attb, const float* xres, const __half* x16,
                       float* outb, __half* outh, int sb){
    k_qk <<<NPVd,256,SM_QK>>>(x16, b_in);
    k_att<<<NN*Sd*PPd,256>>>(attb, alpt);
    k_av <<<NPVd,256,SM_AV>>>(x16, b_out, sb*128);
    k_ffb<<<NPVd,256,SM_FF>>>(xres, b_ff, g_o, be_o, sb*128, (sb+1)*128);
    k_bnres2<<<TOTd/4/256,256>>>(xres, outb, outh, g_o, be_o, g_f, be_f, sb*128, (sb+1)*128);
  };

  run_block(att1, px0, px0h, px1, px1h, 0);
  run_block(att2, px1, px1h, px0, px0h, 2);

  k_tout<<<dim3(256,192), dim3(32,8)>>>(px0, (float*)d_out);
}